// round 8
// baseline (speedup 1.0000x reference)
#include <cuda_runtime.h>
#include <cuda_bf16.h>
#include <math.h>

#define BATCH  8
#define SEQ    1024
#define DMODEL 512
#define NHEAD  8
#define DHEAD  64
#define NLAYER 6
#define DFF    2048
#define NTOK   (BATCH*SEQ)

// ---- mma.sync GEMM tiling (KC=32, 2 CTAs/SM) ----
#define TM 128
#define TN 128
#define KC 32
#define PADK 40                       // padded K columns (40*2 = 80B row = 20 banks)
#define MAT_BYTES (128*PADK*2)        // 10240
#define STAGE_BYTES (4*MAT_BYTES)     // Ahi,Alo,Bhi,Blo = 40960
#define GEMM_SMEM (2*STAGE_BYTES)     // 81920

// ---- flash attention tiling ----
#define FPAD 72
#define NTILE 16
// bf16-element offsets in dynamic smem
#define Q_HI 0
#define Q_LO 9216
#define FSTG(s) (18432 + (s)*18560)
#define KS_HI(s) (FSTG(s))
#define KS_LO(s) (FSTG(s)+4608)
#define VS_HI(s) (FSTG(s)+9216)
#define VS_LO(s) (FSTG(s)+13824)
#define BI_F(s)  (FSTG(s)+18432)      // 64 floats = 128 bf16 elems
#define FLASH_SMEM (2*(18432 + 2*18560))   // 111104 bytes

// ---------------- scratch (device globals) ----------------
__device__ float g_x     [(size_t)NTOK*DMODEL];
__device__ __nv_bfloat16 g_xhi[(size_t)NTOK*DMODEL];
__device__ __nv_bfloat16 g_xlo[(size_t)NTOK*DMODEL];
__device__ __nv_bfloat16 g_qkvhi[(size_t)NTOK*3*DMODEL];
__device__ __nv_bfloat16 g_qkvlo[(size_t)NTOK*3*DMODEL];
__device__ __nv_bfloat16 g_vthi[(size_t)BATCH*NHEAD*DHEAD*SEQ];
__device__ __nv_bfloat16 g_vtlo[(size_t)BATCH*NHEAD*DHEAD*SEQ];
__device__ float g_kbias [(size_t)BATCH*SEQ];
__device__ __nv_bfloat16 g_aohi[(size_t)NTOK*DMODEL];
__device__ __nv_bfloat16 g_aolo[(size_t)NTOK*DMODEL];
__device__ float g_tmp   [(size_t)NTOK*DMODEL];
__device__ __nv_bfloat16 g_fhi[(size_t)NTOK*DFF];
__device__ __nv_bfloat16 g_flo[(size_t)NTOK*DFF];
// transposed bf16 hi/lo weights: layout [N, K] per layer
__device__ __nv_bfloat16 g_wqkvhi[(size_t)NLAYER*3*DMODEL*DMODEL];
__device__ __nv_bfloat16 g_wqkvlo[(size_t)NLAYER*3*DMODEL*DMODEL];
__device__ __nv_bfloat16 g_wfchi [(size_t)NLAYER*DMODEL*DMODEL];
__device__ __nv_bfloat16 g_wfclo [(size_t)NLAYER*DMODEL*DMODEL];
__device__ __nv_bfloat16 g_w1hi  [(size_t)NLAYER*DFF*DMODEL];
__device__ __nv_bfloat16 g_w1lo  [(size_t)NLAYER*DFF*DMODEL];
__device__ __nv_bfloat16 g_w2hi  [(size_t)NLAYER*DMODEL*DFF];
__device__ __nv_bfloat16 g_w2lo  [(size_t)NLAYER*DMODEL*DFF];

// ---------------- helpers ----------------
__device__ __forceinline__ unsigned smem_u32(const void* p){
    unsigned a;
    asm("{ .reg .u64 t; cvta.to.shared.u64 t, %1; cvt.u32.u64 %0, t; }":"=r"(a):"l"(p));
    return a;
}
__device__ __forceinline__ void cp16(unsigned saddr, const void* g){
    asm volatile("cp.async.ca.shared.global [%0], [%1], 16;" :: "r"(saddr), "l"(g));
}
#define CP_COMMIT() asm volatile("cp.async.commit_group;" ::: "memory")
template<int N> __device__ __forceinline__ void cp_wait(){
    asm volatile("cp.async.wait_group %0;" :: "n"(N) : "memory");
}
__device__ __forceinline__ void mma16816(float* d, const unsigned* a, const unsigned* b){
    asm volatile(
        "mma.sync.aligned.m16n8k16.row.col.f32.bf16.bf16.f32 "
        "{%0,%1,%2,%3}, {%4,%5,%6,%7}, {%8,%9}, {%0,%1,%2,%3};"
        : "+f"(d[0]), "+f"(d[1]), "+f"(d[2]), "+f"(d[3])
        : "r"(a[0]), "r"(a[1]), "r"(a[2]), "r"(a[3]), "r"(b[0]), "r"(b[1]));
}
__device__ __forceinline__ unsigned ld2bf(const __nv_bfloat16* p){
    return *(const unsigned*)p;
}
__device__ __forceinline__ void split_bf16(float v, __nv_bfloat16& h, __nv_bfloat16& l){
    h = __float2bfloat16(v);
    l = __float2bfloat16(v - __bfloat162float(h));
}
// split two floats into packed bf16x2 hi and lo words
__device__ __forceinline__ void split2(float a, float b, unsigned& hi, unsigned& lo){
    __nv_bfloat16 ha = __float2bfloat16(a), hb = __float2bfloat16(b);
    __nv_bfloat162 hp; hp.x = ha; hp.y = hb;
    __nv_bfloat162 lp;
    lp.x = __float2bfloat16(a - __bfloat162float(ha));
    lp.y = __float2bfloat16(b - __bfloat162float(hb));
    hi = *(unsigned*)&hp; lo = *(unsigned*)&lp;
}

// ---------------- weight prep: W[L][K][N] fp32 -> T[L][N][K] bf16 hi/lo (tiled transpose) ----------------
__global__ __launch_bounds__(256) void wprep_kernel(const float* __restrict__ W,
                             __nv_bfloat16* __restrict__ Thi,
                             __nv_bfloat16* __restrict__ Tlo,
                             int K, int N)
{
    __shared__ float tf[32][33];
    const int l = blockIdx.z;
    const int n0 = blockIdx.x*32, k0 = blockIdx.y*32;
    const int tx = threadIdx.x & 31, ty = threadIdx.x >> 5;
    const float* Wl = W + (size_t)l*K*N;
#pragma unroll
    for (int i = 0; i < 4; i++) {
        int k = k0 + ty*4 + i;
        tf[ty*4+i][tx] = Wl[(size_t)k*N + n0 + tx];
    }
    __syncthreads();
    __nv_bfloat16* Th = Thi + (size_t)l*K*N;
    __nv_bfloat16* Tl = Tlo + (size_t)l*K*N;
#pragma unroll
    for (int i = 0; i < 4; i++) {
        int n = n0 + ty*4 + i;
        float v = tf[tx][ty*4+i];
        __nv_bfloat16 h, lo; split_bf16(v, h, lo);
        Th[(size_t)n*K + k0 + tx] = h;
        Tl[(size_t)n*K + k0 + tx] = lo;
    }
}

// ---------------- mma.sync split-bf16 GEMM (2 CTAs/SM) ----------------
// C[M,N] = A[M,K] @ B^T ; A as hi/lo [M,K], B as hi/lo [N,K].
// EPI: 1 +bias fp32; 2 +bias+relu bf16-pair; 3 bf16-pair (no bias).
template<int EPI>
__global__ __launch_bounds__(256, 2) void mma_gemm_kernel(
    const __nv_bfloat16* __restrict__ Ahi, const __nv_bfloat16* __restrict__ Alo,
    const __nv_bfloat16* __restrict__ Bhi, const __nv_bfloat16* __restrict__ Blo,
    const float* __restrict__ bias,
    float* __restrict__ Cf,
    __nv_bfloat16* __restrict__ Chi, __nv_bfloat16* __restrict__ Clo,
    int N, int K)
{
    extern __shared__ char smem[];
    const unsigned sbase = smem_u32(smem);
    const int tid = threadIdx.x;
    const int wid = tid >> 5, lane = tid & 31;
    const int wr = wid & 3;
    const int wc = wid >> 2;
    const int bm = blockIdx.y * TM;
    const int bn = blockIdx.x * TN;

    // loaders: 512 x 16B per matrix per chunk; 2 per thread
    const int lr = tid >> 2;          // row 0..63 (then +64)
    const int lg = tid & 3;           // 16B group within 64B row

    float acc[2][8][4];
#pragma unroll
    for (int ma = 0; ma < 2; ma++)
#pragma unroll
        for (int na = 0; na < 8; na++)
#pragma unroll
            for (int j = 0; j < 4; j++) acc[ma][na][j] = 0.0f;

    const int NC = K >> 5;

    {
        const unsigned st = sbase;
#pragma unroll
        for (int i = 0; i < 2; i++) {
            int r = lr + i*64;
            unsigned so = (unsigned)(r*80 + lg*16);
            size_t ga = (size_t)(bm + r)*K + lg*8;
            size_t gb = (size_t)(bn + r)*K + lg*8;
            cp16(st + so,                 Ahi + ga);
            cp16(st + MAT_BYTES + so,     Alo + ga);
            cp16(st + 2*MAT_BYTES + so,   Bhi + gb);
            cp16(st + 3*MAT_BYTES + so,   Blo + gb);
        }
        CP_COMMIT();
    }

    for (int c = 0; c < NC; c++) {
        if (c + 1 < NC) {
            const unsigned st = sbase + ((c+1) & 1)*STAGE_BYTES;
            const int k0 = (c+1)*KC;
#pragma unroll
            for (int i = 0; i < 2; i++) {
                int r = lr + i*64;
                unsigned so = (unsigned)(r*80 + lg*16);
                size_t ga = (size_t)(bm + r)*K + k0 + lg*8;
                size_t gb = (size_t)(bn + r)*K + k0 + lg*8;
                cp16(st + so,                 Ahi + ga);
                cp16(st + MAT_BYTES + so,     Alo + ga);
                cp16(st + 2*MAT_BYTES + so,   Bhi + gb);
                cp16(st + 3*MAT_BYTES + so,   Blo + gb);
            }
            CP_COMMIT();
            cp_wait<1>();
        } else {
            cp_wait<0>();
        }
        __syncthreads();

        const char* stg = smem + (c & 1)*STAGE_BYTES;
        const __nv_bfloat16* sAh = (const __nv_bfloat16*)(stg);
        const __nv_bfloat16* sAl = (const __nv_bfloat16*)(stg + MAT_BYTES);
        const __nv_bfloat16* sBh = (const __nv_bfloat16*)(stg + 2*MAT_BYTES);
        const __nv_bfloat16* sBl = (const __nv_bfloat16*)(stg + 3*MAT_BYTES);

#pragma unroll
        for (int ks = 0; ks < 2; ks++) {
            const int kk = ks*16 + (lane & 3)*2;
            unsigned ah[2][4], al[2][4];
#pragma unroll
            for (int ma = 0; ma < 2; ma++) {
                const int r0 = wr*32 + ma*16 + (lane >> 2);
                ah[ma][0] = ld2bf(sAh + r0*PADK + kk);
                ah[ma][1] = ld2bf(sAh + (r0+8)*PADK + kk);
                ah[ma][2] = ld2bf(sAh + r0*PADK + kk + 8);
                ah[ma][3] = ld2bf(sAh + (r0+8)*PADK + kk + 8);
                al[ma][0] = ld2bf(sAl + r0*PADK + kk);
                al[ma][1] = ld2bf(sAl + (r0+8)*PADK + kk);
                al[ma][2] = ld2bf(sAl + r0*PADK + kk + 8);
                al[ma][3] = ld2bf(sAl + (r0+8)*PADK + kk + 8);
            }
            // process n-atoms in halves of 4 to bound register pressure;
            // same-accumulator MMA distance = 8 (2 ma x 4 na per product pass)
#pragma unroll
            for (int hb = 0; hb < 2; hb++) {
                unsigned bh[4][2], bl[4][2];
#pragma unroll
                for (int j = 0; j < 4; j++) {
                    const int n0 = wc*64 + (hb*4 + j)*8 + (lane >> 2);
                    bh[j][0] = ld2bf(sBh + n0*PADK + kk);
                    bh[j][1] = ld2bf(sBh + n0*PADK + kk + 8);
                    bl[j][0] = ld2bf(sBl + n0*PADK + kk);
                    bl[j][1] = ld2bf(sBl + n0*PADK + kk + 8);
                }
#pragma unroll
                for (int ma = 0; ma < 2; ma++)
#pragma unroll
                    for (int j = 0; j < 4; j++)
                        mma16816(acc[ma][hb*4+j], ah[ma], bh[j]);
#pragma unroll
                for (int ma = 0; ma < 2; ma++)
#pragma unroll
                    for (int j = 0; j < 4; j++)
                        mma16816(acc[ma][hb*4+j], ah[ma], bl[j]);
#pragma unroll
                for (int ma = 0; ma < 2; ma++)
#pragma unroll
                    for (int j = 0; j < 4; j++)
                        mma16816(acc[ma][hb*4+j], al[ma], bh[j]);
            }
        }
        __syncthreads();
    }

    constexpr bool HASBIAS = (EPI == 1 || EPI == 2);
    constexpr bool RELU    = (EPI == 2);
    constexpr bool PAIR    = (EPI == 2 || EPI == 3);
#pragma unroll
    for (int ma = 0; ma < 2; ma++) {
        const int r0 = bm + wr*32 + ma*16 + (lane >> 2);
#pragma unroll
        for (int na = 0; na < 8; na++) {
            const int cc = bn + wc*64 + na*8 + (lane & 3)*2;
            float v0 = acc[ma][na][0], v1 = acc[ma][na][1];
            float v2 = acc[ma][na][2], v3 = acc[ma][na][3];
            if (HASBIAS) {
                float2 bv = *(const float2*)(bias + cc);
                v0 += bv.x; v1 += bv.y; v2 += bv.x; v3 += bv.y;
            }
            if (RELU) {
                v0 = fmaxf(v0, 0.0f); v1 = fmaxf(v1, 0.0f);
                v2 = fmaxf(v2, 0.0f); v3 = fmaxf(v3, 0.0f);
            }
            if (PAIR) {
                unsigned hi, lo;
                split2(v0, v1, hi, lo);
                *(unsigned*)(Chi + (size_t)r0*N + cc) = hi;
                *(unsigned*)(Clo + (size_t)r0*N + cc) = lo;
                split2(v2, v3, hi, lo);
                *(unsigned*)(Chi + (size_t)(r0+8)*N + cc) = hi;
                *(unsigned*)(Clo + (size_t)(r0+8)*N + cc) = lo;
            } else {
                *(float2*)(Cf + (size_t)r0*N + cc)     = make_float2(v0, v1);
                *(float2*)(Cf + (size_t)(r0+8)*N + cc) = make_float2(v2, v3);
            }
        }
    }
}

// ---------------- V transpose: qkv pair [B,S, V@1024+h*64] -> vt [bh][dh][seq] ----------------
// 64 seq x 32 dh tiles; packed 4B coalesced writes.
__global__ __launch_bounds__(256) void vtrans_kernel(
    const __nv_bfloat16* __restrict__ qhi, const __nv_bfloat16* __restrict__ qlo,
    __nv_bfloat16* __restrict__ vthi, __nv_bfloat16* __restrict__ vtlo)
{
    __shared__ __nv_bfloat16 th[64][33], tl[64][33];
    const int bh = blockIdx.z, b = bh >> 3, h = bh & 7;
    const int s0 = blockIdx.x*64, d0 = blockIdx.y*32;
    const int tx = threadIdx.x & 31, ty = threadIdx.x >> 5;
#pragma unroll
    for (int i = 0; i < 8; i++) {
        int sr = ty*8 + i;
        size_t g = (size_t)(b*SEQ + s0 + sr)*1536 + 1024 + h*64 + d0 + tx;
        th[sr][tx] = qhi[g];
        tl[sr][tx] = qlo[g];
    }
    __syncthreads();
#pragma unroll
    for (int i = 0; i < 4; i++) {
        int dr = ty*4 + i;
        size_t g = ((size_t)bh*64 + d0 + dr)*1024 + s0 + tx*2;
        __nv_bfloat162 hp, lp;
        hp.x = th[tx*2][dr]; hp.y = th[tx*2+1][dr];
        lp.x = tl[tx*2][dr]; lp.y = tl[tx*2+1][dr];
        *(__nv_bfloat162*)(vthi + g) = hp;
        *(__nv_bfloat162*)(vtlo + g) = lp;
    }
}

// ---------------- fused flash attention (split-bf16 mma, online softmax) ----------------
__global__ __launch_bounds__(256, 2) void flash_kernel(
    const __nv_bfloat16* __restrict__ qhi, const __nv_bfloat16* __restrict__ qlo,
    const __nv_bfloat16* __restrict__ vthi, const __nv_bfloat16* __restrict__ vtlo,
    const float* __restrict__ kbias,
    __nv_bfloat16* __restrict__ ohi, __nv_bfloat16* __restrict__ olo)
{
    extern __shared__ char smraw[];
    __nv_bfloat16* sm = (__nv_bfloat16*)smraw;
    const unsigned sb = smem_u32(sm);
    const int tid = threadIdx.x, wid = tid >> 5, lane = tid & 31;
    const int bh = blockIdx.y, b = bh >> 3, h = bh & 7;
    const int q0 = blockIdx.x * 128;
    const int koff = (lane & 3)*2;
    const int r_base = wid*16 + (lane >> 2);

    auto prefetch_kv = [&](int t, int s){
        const int g = tid & 7;
        const int kt0 = t*64;
#pragma unroll
        for (int i = 0; i < 2; i++) {
            int r = (tid >> 3) + i*32;
            size_t gk = (size_t)(b*SEQ + kt0 + r)*1536 + 512 + h*64 + g*8;
            cp16(sb + 2*(KS_HI(s) + r*FPAD + g*8), qhi + gk);
            cp16(sb + 2*(KS_LO(s) + r*FPAD + g*8), qlo + gk);
            size_t gv = ((size_t)bh*64 + r)*1024 + kt0 + g*8;
            cp16(sb + 2*(VS_HI(s) + r*FPAD + g*8), vthi + gv);
            cp16(sb + 2*(VS_LO(s) + r*FPAD + g*8), vtlo + gv);
        }
        if (tid >= 240) {
            int j = tid - 240;
            cp16(sb + 2*BI_F(s) + j*16, kbias + b*SEQ + kt0 + j*4);
        }
    };

    // prefetch Q + tile 0 (commit group 0)
    {
        const int g = tid & 7;
#pragma unroll
        for (int i = 0; i < 4; i++) {
            int r = (tid >> 3) + i*32;
            size_t gq = (size_t)(b*SEQ + q0 + r)*1536 + h*64 + g*8;
            cp16(sb + 2*(Q_HI + r*FPAD + g*8), qhi + gq);
            cp16(sb + 2*(Q_LO + r*FPAD + g*8), qlo + gq);
        }
        prefetch_kv(0, 0);
        CP_COMMIT();
    }

    float m0 = -1e30f, m1 = -1e30f, l0 = 0.0f, l1 = 0.0f;
    float acc_o[8][4];
#pragma unroll
    for (int na = 0; na < 8; na++)
#pragma unroll
        for (int j = 0; j < 4; j++) acc_o[na][j] = 0.0f;

    for (int t = 0; t < NTILE; t++) {
        if (t + 1 < NTILE) { prefetch_kv(t+1, (t+1)&1); CP_COMMIT(); cp_wait<1>(); }
        else               { cp_wait<0>(); }
        __syncthreads();
        const int s = t & 1;
        const __nv_bfloat16* Kh = sm + KS_HI(s);
        const __nv_bfloat16* Kl = sm + KS_LO(s);
        const __nv_bfloat16* Vh = sm + VS_HI(s);
        const __nv_bfloat16* Vl = sm + VS_LO(s);
        const float* bsm = (const float*)(sm + BI_F(s));

        // S = Q K^T (3-product split)
        float sc[8][4];
#pragma unroll
        for (int na = 0; na < 8; na++)
#pragma unroll
            for (int j = 0; j < 4; j++) sc[na][j] = 0.0f;

#pragma unroll
        for (int kc = 0; kc < 4; kc++) {
            const int k2 = kc*16 + koff;
            unsigned ah[4], al[4];
            ah[0] = ld2bf(sm + Q_HI + r_base*FPAD + k2);
            ah[1] = ld2bf(sm + Q_HI + (r_base+8)*FPAD + k2);
            ah[2] = ld2bf(sm + Q_HI + r_base*FPAD + k2 + 8);
            ah[3] = ld2bf(sm + Q_HI + (r_base+8)*FPAD + k2 + 8);
            al[0] = ld2bf(sm + Q_LO + r_base*FPAD + k2);
            al[1] = ld2bf(sm + Q_LO + (r_base+8)*FPAD + k2);
            al[2] = ld2bf(sm + Q_LO + r_base*FPAD + k2 + 8);
            al[3] = ld2bf(sm + Q_LO + (r_base+8)*FPAD + k2 + 8);
#pragma unroll
            for (int na = 0; na < 8; na++) {
                const int n = na*8 + (lane >> 2);
                unsigned bh2[2], bl2[2];
                bh2[0] = ld2bf(Kh + n*FPAD + k2);
                bh2[1] = ld2bf(Kh + n*FPAD + k2 + 8);
                bl2[0] = ld2bf(Kl + n*FPAD + k2);
                bl2[1] = ld2bf(Kl + n*FPAD + k2 + 8);
                mma16816(sc[na], ah, bh2);
                mma16816(sc[na], ah, bl2);
                mma16816(sc[na], al, bh2);
            }
        }

        // key-mask bias
#pragma unroll
        for (int na = 0; na < 8; na++) {
            float b0 = bsm[na*8 + koff], b1 = bsm[na*8 + koff + 1];
            sc[na][0] += b0; sc[na][1] += b1;
            sc[na][2] += b0; sc[na][3] += b1;
        }

        // online softmax (rows r_base and r_base+8)
        float mx0 = -1e30f, mx1 = -1e30f;
#pragma unroll
        for (int na = 0; na < 8; na++) {
            mx0 = fmaxf(mx0, fmaxf(sc[na][0], sc[na][1]));
            mx1 = fmaxf(mx1, fmaxf(sc[na][2], sc[na][3]));
        }
        mx0 = fmaxf(mx0, __shfl_xor_sync(0xffffffffu, mx0, 1));
        mx0 = fmaxf(mx0, __shfl_xor_sync(0xffffffffu, mx0, 2));
        mx1 = fmaxf(mx1, __shfl_xor_sync(0xffffffffu, mx1, 1));
        mx1 = fmaxf(mx1, __shfl_xor_sync(0xffffffffu, mx1, 2));
        float mn0 = fmaxf(m0, mx0), mn1 = fmaxf(m1, mx1);
        float e0 = __expf(m0 - mn0), e1 = __expf(m1 - mn1);
        m0 = mn0; m1 = mn1;
        float s0 = 0.0f, s1 = 0.0f;
#pragma unroll
        for (int na = 0; na < 8; na++) {
            sc[na][0] = __expf(sc[na][0] - mn0);
            sc[na][1] = __expf(sc[na][1] - mn0);
            sc[na][2] = __expf(sc[na][2] - mn1);
            sc[na][3] = __expf(sc[na][3] - mn1);
            s0 += sc[na][0] + sc[na][1];
            s1 += sc[na][2] + sc[na][3];
        }
        s0 += __shfl_xor_sync(0xffffffffu, s0, 1);
        s0 += __shfl_xor_sync(0xffffffffu, s0, 2);
        s1 += __shfl_xor_sync(0xffffffffu, s1, 1);
        s1 += __shfl_xor_sync(0xffffffffu, s1, 2);
        l0 = l0*e0 + s0;
        l1 = l1*e1 + s1;
#pragma unroll
        for (int na = 0; na < 8; na++) {
            acc_o[na][0] *= e0; acc_o[na][1] *= e0;
            acc_o[na][2] *= e1; acc_o[na][3] *= e1;
        }

        // O += P V (3-product split; P frags from registers)
#pragma unroll
        for (int kc = 0; kc < 4; kc++) {
            unsigned ph[4], pl[4];
            split2(sc[2*kc][0],   sc[2*kc][1],   ph[0], pl[0]);
            split2(sc[2*kc][2],   sc[2*kc][3],   ph[1], pl[1]);
            split2(sc[2*kc+1][0], sc[2*kc+1][1], ph[2], pl[2]);
            split2(sc[2*kc+1][2], sc[2*kc+1][3], ph[3], pl[3]);
            const int k2 = kc*16 + koff;
#pragma unroll
            for (int na = 0; na < 8; na++) {
                const int n = na*8 + (lane >> 2);
                unsigned vh2[2], vl2[2];
                vh2[0] = ld2bf(Vh + n*FPAD + k2);
                vh2[1] = ld2bf(Vh + n*FPAD + k2 + 8);
                vl2[0] = ld2bf(Vl + n*FPAD + k2);
                vl2[1] = ld2bf(Vl + n*FPAD + k2 + 8);
                mma16816(acc_o[na], ph, vh2);
                mma16816(acc_o[na], ph, vl2);
                mma16816(acc_o[na], pl, vh2);
            }
        }
        __syncthreads();
    }

    // epilogue: O /= l, write bf16 hi/lo pair at [b, q0+row, h*64+col]
    const float inv0 = 1.0f / l0, inv1 = 1.0f / l1;
    const size_t row0 = (size_t)(b*SEQ + q0 + r_base);
#pragma unroll
    for (int na = 0; na < 8; na++) {
        const int col = h*64 + na*8 + koff;
        unsigned hi, lo;
        split2(acc_o[na][0]*inv0, acc_o[na][1]*inv0, hi, lo);
        *(unsigned*)(ohi + row0*DMODEL + col) = hi;
        *(unsigned*)(olo + row0*DMODEL + col) = lo;
        split2(acc_o[na][2]*inv1, acc_o[na][3]*inv1, hi, lo);
        *(unsigned*)(ohi + (row0+8)*DMODEL + col) = hi;
        *(unsigned*)(olo + (row0+8)*DMODEL + col) = lo;
    }
}

// ---------------- positional embedding + pair split + key-mask bias ----------------
__global__ void posembed_kernel(const float* __restrict__ xin,
                                const int* __restrict__ mask,
                                float* __restrict__ xout,
                                __nv_bfloat16* __restrict__ xhi,
                                __nv_bfloat16* __restrict__ xlo,
                                float* __restrict__ kb)
{
    int b = blockIdx.x;
    int tid = threadIdx.x;                    // 1024 threads
    __shared__ int sc[SEQ];
    int valid = (mask[b*SEQ + tid] != 0) ? 1 : 0;
    kb[b*SEQ + tid] = valid ? 0.0f : -1e30f;
    sc[tid] = valid;
    __syncthreads();
    for (int off = 1; off < SEQ; off <<= 1) {
        int v = (tid >= off) ? sc[tid - off] : 0;
        __syncthreads();
        sc[tid] += v;
        __syncthreads();
    }
    int pos = sc[tid] * valid;
    __syncthreads();
    sc[tid] = pos;
    __syncthreads();

    const float cfreq = -logf(10000.0f) / 255.0f;
    for (int it = 0; it < (SEQ*DMODEL)/SEQ; it++) {
        int idx = it*SEQ + tid;
        int s = idx >> 9;
        int j = idx & 511;
        int p = sc[s];
        size_t g = ((size_t)b*SEQ + s)*DMODEL + j;
        float add = 0.0f;
        if (p > 0) {
            float fr  = expf((float)(j & 255) * cfreq);
            float ang = (float)p * fr;
            add = (j < 256) ? sinf(ang) : cosf(ang);
        }
        float v = xin[g] + add;
        xout[g] = v;
        __nv_bfloat16 h, l; split_bf16(v, h, l);
        xhi[g] = h; xlo[g] = l;
    }
}

// ---------------- out = LN(a + r) * g + b ; warp-per-row, shfl-only ----------------
__global__ __launch_bounds__(256) void ln_kernel(
    const float* __restrict__ a, const float* __restrict__ r,
    const float* __restrict__ g, const float* __restrict__ be,
    float* __restrict__ out,
    __nv_bfloat16* __restrict__ ohi, __nv_bfloat16* __restrict__ olo)
{
    const int row = blockIdx.x*8 + (threadIdx.x >> 5);
    const int lane = threadIdx.x & 31;
    const size_t base = (size_t)row*DMODEL;
    const float4* a4 = (const float4*)(a + base);
    const float4* r4 = (const float4*)(r + base);

    float4 x[4];
    float s = 0.0f;
#pragma unroll
    for (int k = 0; k < 4; k++) {
        float4 va = a4[lane + k*32];
        float4 vr = r4[lane + k*32];
        x[k] = make_float4(va.x+vr.x, va.y+vr.y, va.z+vr.z, va.w+vr.w);
        s += x[k].x + x[k].y + x[k].z + x[k].w;
    }
#pragma unroll
    for (int o = 16; o; o >>= 1) s += __shfl_xor_sync(0xffffffffu, s, o);
    const float mu = s * (1.0f/512.0f);

    float s2 = 0.0f;
#pragma unroll
    for (int k = 0; k < 4; k++) {
        x[k].x -= mu; x[k].y -= mu; x[k].z -= mu; x[k].w -= mu;
        s2 += x[k].x*x[k].x + x[k].y*x[k].y + x[k].z*x[k].z + x[k].w*x[k].w;
    }
#pragma unroll
    for (int o = 16; o; o >>= 1) s2 += __shfl_xor_sync(0xffffffffu, s2, o);
    const float inv = rsqrtf(s2 * (1.0f/512.0f) + 1e-5f);

    const float4* g4 = (const float4*)g;
    const float4* b4 = (const float4*)be;
    float4* o4 = (float4*)(out + base);
    uint2* oh2 = (uint2*)(ohi + base);
    uint2* ol2 = (uint2*)(olo + base);
#pragma unroll
    for (int k = 0; k < 4; k++) {
        float4 gg = g4[lane + k*32];
        float4 bb = b4[lane + k*32];
        float4 o;
        o.x = x[k].x*inv*gg.x + bb.x;
        o.y = x[k].y*inv*gg.y + bb.y;
        o.z = x[k].z*inv*gg.z + bb.z;
        o.w = x[k].w*inv*gg.w + bb.w;
        o4[lane + k*32] = o;
        unsigned h0, l0, h1, l1;
        split2(o.x, o.y, h0, l0);
        split2(o.z, o.w, h1, l1);
        oh2[lane + k*32] = make_uint2(h0, h1);
        ol2[lane + k*32] = make_uint2(l0, l1);
    }
}

// ---------------- driver ----------------
extern "C" void kernel_launch(void* const* d_in, const int* in_sizes, int n_in,
                              void* d_out, int out_size)
{
    const float* x_in = (const float*)d_in[0];
    const int*   mask = (const int*)d_in[3];
    const float* Wqkv = (const float*)d_in[4];
    const float* Wfc  = (const float*)d_in[5];
    const float* bfc  = (const float*)d_in[6];
    const float* ln1g = (const float*)d_in[7];
    const float* ln1b = (const float*)d_in[8];
    const float* ln2g = (const float*)d_in[9];
    const float* ln2b = (const float*)d_in[10];
    const float* W1   = (const float*)d_in[11];
    const float* b1   = (const float*)d_in[12];
    const float* W2   = (const float*)d_in[13];
    const float* b2   = (const float*)d_in[14];

    float *px, *ptmp, *pkb;
    __nv_bfloat16 *pxhi, *pxlo, *pqh, *pql, *pvth, *pvtl, *paohi, *paolo, *pfhi, *pflo;
    __nv_bfloat16 *wqh, *wql, *wfh, *wfl, *w1h, *w1l, *w2h, *w2l;
    cudaGetSymbolAddress((void**)&px,    g_x);
    cudaGetSymbolAddress((void**)&pxhi,  g_xhi);
    cudaGetSymbolAddress((void**)&pxlo,  g_xlo);
    cudaGetSymbolAddress((void**)&pqh,   g_qkvhi);
    cudaGetSymbolAddress((void**)&pql,   g_qkvlo);
    cudaGetSymbolAddress((void**)&pvth,  g_vthi);
    cudaGetSymbolAddress((void**)&pvtl,  g_vtlo);
    cudaGetSymbolAddress((void**)&pkb,   g_kbias);
    cudaGetSymbolAddress((void**)&paohi, g_aohi);
    cudaGetSymbolAddress((void**)&paolo, g_aolo);
    cudaGetSymbolAddress((void**)&ptmp,  g_tmp);
    cudaGetSymbolAddress((void**)&pfhi,  g_fhi);
    cudaGetSymbolAddress((void**)&pflo,  g_flo);
    cudaGetSymbolAddress((void**)&wqh,   g_wqkvhi);
    cudaGetSymbolAddress((void**)&wql,   g_wqkvlo);
    cudaGetSymbolAddress((void**)&wfh,   g_wfchi);
    cudaGetSymbolAddress((void**)&wfl,   g_wfclo);
    cudaGetSymbolAddress((void**)&w1h,   g_w1hi);
    cudaGetSymbolAddress((void**)&w1l,   g_w1lo);
    cudaGetSymbolAddress((void**)&w2h,   g_w2hi);
    cudaGetSymbolAddress((void**)&w2l,   g_w2lo);

    cudaFuncSetAttribute(mma_gemm_kernel<1>, cudaFuncAttributeMaxDynamicSharedMemorySize, GEMM_SMEM);
    cudaFuncSetAttribute(mma_gemm_kernel<2>, cudaFuncAttributeMaxDynamicSharedMemorySize, GEMM_SMEM);
    cudaFuncSetAttribute(mma_gemm_kernel<3>, cudaFuncAttributeMaxDynamicSharedMemorySize, GEMM_SMEM);
    cudaFuncSetAttribute(flash_kernel, cudaFuncAttributeMaxDynamicSharedMemorySize, FLASH_SMEM);

    // weight prep: tiled transpose + split, all layers per launch
    wprep_kernel<<<dim3(3*DMODEL/32, DMODEL/32, NLAYER), 256>>>(Wqkv, wqh, wql, DMODEL, 3*DMODEL);
    wprep_kernel<<<dim3(DMODEL/32,   DMODEL/32, NLAYER), 256>>>(Wfc,  wfh, wfl, DMODEL, DMODEL);
    wprep_kernel<<<dim3(DFF/32,      DMODEL/32, NLAYER), 256>>>(W1,   w1h, w1l, DMODEL, DFF);
    wprep_kernel<<<dim3(DMODEL/32,   DFF/32,    NLAYER), 256>>>(W2,   w2h, w2l, DFF, DMODEL);

    posembed_kernel<<<BATCH, SEQ>>>(x_in, mask, px, pxhi, pxlo, pkb);

    for (int l = 0; l < NLAYER; l++) {
        size_t oq = (size_t)l*3*DMODEL*DMODEL;
        size_t of = (size_t)l*DMODEL*DMODEL;
        size_t o1 = (size_t)l*DFF*DMODEL;
        size_t o2 = (size_t)l*DMODEL*DFF;
        // QKV -> bf16 hi/lo pair
        mma_gemm_kernel<3><<<dim3(3*DMODEL/TN, NTOK/TM), 256, GEMM_SMEM>>>(
            pxhi, pxlo, wqh + oq, wql + oq, nullptr, nullptr, pqh, pql, 3*DMODEL, DMODEL);
        // V transpose for flash B-operand
        vtrans_kernel<<<dim3(SEQ/64, DHEAD/32, BATCH*NHEAD), 256>>>(pqh, pql, pvth, pvtl);
        // fused attention
        flash_kernel<<<dim3(SEQ/128, BATCH*NHEAD), 256, FLASH_SMEM>>>(
            pqh, pql, pvth, pvtl, pkb, paohi, paolo);
        // proj + bias -> fp32
        mma_gemm_kernel<1><<<dim3(DMODEL/TN, NTOK/TM), 256, GEMM_SMEM>>>(
            paohi, paolo, wfh + of, wfl + of, bfc + l*DMODEL, ptmp, nullptr, nullptr, DMODEL, DMODEL);
        ln_kernel<<<NTOK/8, 256>>>(ptmp, px, ln1g + l*DMODEL, ln1b + l*DMODEL, px, pxhi, pxlo);
        // FFN up + relu -> bf16 pair
        mma_gemm_kernel<2><<<dim3(DFF/TN, NTOK/TM), 256, GEMM_SMEM>>>(
            pxhi, pxlo, w1h + o1, w1l + o1, b1 + l*DFF, nullptr, pfhi, pflo, DFF, DMODEL);
        // FFN down + bias -> fp32
        mma_gemm_kernel<1><<<dim3(DMODEL/TN, NTOK/TM), 256, GEMM_SMEM>>>(
            pfhi, pflo, w2h + o2, w2l + o2, b2 + l*DMODEL, ptmp, nullptr, nullptr, DMODEL, DFF);
        ln_kernel<<<NTOK/8, 256>>>(ptmp, px, ln2g + l*DMODEL, ln2b + l*DMODEL, px, pxhi, pxlo);
    }

    cudaMemcpyAsync(d_out, px, (size_t)NTOK*DMODEL*sizeof(float),
                    cudaMemcpyDeviceToDevice);
}

// round 9
// speedup vs baseline: 1.0430x; 1.0430x over previous
#include <cuda_runtime.h>
#include <cuda_bf16.h>
#include <math.h>

#define BATCH  8
#define SEQ    1024
#define DMODEL 512
#define NHEAD  8
#define DHEAD  64
#define NLAYER 6
#define DFF    2048
#define NTOK   (BATCH*SEQ)

// ---- mma.sync GEMM tiling: CTA 128x256, warp grid 2x4 of 64x64, KC=64 ----
#define TM 128
#define TN 256
#define KC 64
#define PADK 72                        // 72 bf16 = 144B row = 36 banks (conflict-free, R5-verified)
#define A_MAT 18432                    // 128*72*2
#define B_MAT 36864                    // 256*72*2
#define STAGE_BYTES (2*A_MAT + 2*B_MAT)  // 110592
#define GEMM_SMEM (2*STAGE_BYTES)        // 221184
// stage-relative byte offsets
#define OFF_AHI 0
#define OFF_ALO A_MAT
#define OFF_BHI (2*A_MAT)
#define OFF_BLO (2*A_MAT + B_MAT)

// ---- flash attention tiling ----
#define FPAD 72
#define NTILE 16
#define Q_HI 0
#define Q_LO 9216
#define FSTG(s) (18432 + (s)*18560)
#define KS_HI(s) (FSTG(s))
#define KS_LO(s) (FSTG(s)+4608)
#define VS_HI(s) (FSTG(s)+9216)
#define VS_LO(s) (FSTG(s)+13824)
#define BI_F(s)  (FSTG(s)+18432)
#define FLASH_SMEM (2*(18432 + 2*18560))   // 111104 bytes

// ---------------- scratch (device globals) ----------------
__device__ float g_x     [(size_t)NTOK*DMODEL];
__device__ __nv_bfloat16 g_xhi[(size_t)NTOK*DMODEL];
__device__ __nv_bfloat16 g_xlo[(size_t)NTOK*DMODEL];
__device__ __nv_bfloat16 g_qkvhi[(size_t)NTOK*3*DMODEL];
__device__ __nv_bfloat16 g_qkvlo[(size_t)NTOK*3*DMODEL];
__device__ __nv_bfloat16 g_vthi[(size_t)BATCH*NHEAD*DHEAD*SEQ];
__device__ __nv_bfloat16 g_vtlo[(size_t)BATCH*NHEAD*DHEAD*SEQ];
__device__ float g_kbias [(size_t)BATCH*SEQ];
__device__ __nv_bfloat16 g_aohi[(size_t)NTOK*DMODEL];
__device__ __nv_bfloat16 g_aolo[(size_t)NTOK*DMODEL];
__device__ float g_tmp   [(size_t)NTOK*DMODEL];
__device__ __nv_bfloat16 g_fhi[(size_t)NTOK*DFF];
__device__ __nv_bfloat16 g_flo[(size_t)NTOK*DFF];
__device__ __nv_bfloat16 g_wqkvhi[(size_t)NLAYER*3*DMODEL*DMODEL];
__device__ __nv_bfloat16 g_wqkvlo[(size_t)NLAYER*3*DMODEL*DMODEL];
__device__ __nv_bfloat16 g_wfchi [(size_t)NLAYER*DMODEL*DMODEL];
__device__ __nv_bfloat16 g_wfclo [(size_t)NLAYER*DMODEL*DMODEL];
__device__ __nv_bfloat16 g_w1hi  [(size_t)NLAYER*DFF*DMODEL];
__device__ __nv_bfloat16 g_w1lo  [(size_t)NLAYER*DFF*DMODEL];
__device__ __nv_bfloat16 g_w2hi  [(size_t)NLAYER*DMODEL*DFF];
__device__ __nv_bfloat16 g_w2lo  [(size_t)NLAYER*DMODEL*DFF];

// ---------------- helpers ----------------
__device__ __forceinline__ unsigned smem_u32(const void* p){
    unsigned a;
    asm("{ .reg .u64 t; cvta.to.shared.u64 t, %1; cvt.u32.u64 %0, t; }":"=r"(a):"l"(p));
    return a;
}
__device__ __forceinline__ void cp16(unsigned saddr, const void* g){
    asm volatile("cp.async.ca.shared.global [%0], [%1], 16;" :: "r"(saddr), "l"(g));
}
#define CP_COMMIT() asm volatile("cp.async.commit_group;" ::: "memory")
template<int N> __device__ __forceinline__ void cp_wait(){
    asm volatile("cp.async.wait_group %0;" :: "n"(N) : "memory");
}
__device__ __forceinline__ void mma16816(float* d, const unsigned* a, const unsigned* b){
    asm volatile(
        "mma.sync.aligned.m16n8k16.row.col.f32.bf16.bf16.f32 "
        "{%0,%1,%2,%3}, {%4,%5,%6,%7}, {%8,%9}, {%0,%1,%2,%3};"
        : "+f"(d[0]), "+f"(d[1]), "+f"(d[2]), "+f"(d[3])
        : "r"(a[0]), "r"(a[1]), "r"(a[2]), "r"(a[3]), "r"(b[0]), "r"(b[1]));
}
__device__ __forceinline__ unsigned ld2bf(const __nv_bfloat16* p){
    return *(const unsigned*)p;
}
__device__ __forceinline__ void split_bf16(float v, __nv_bfloat16& h, __nv_bfloat16& l){
    h = __float2bfloat16(v);
    l = __float2bfloat16(v - __bfloat162float(h));
}
__device__ __forceinline__ void split2(float a, float b, unsigned& hi, unsigned& lo){
    __nv_bfloat16 ha = __float2bfloat16(a), hb = __float2bfloat16(b);
    __nv_bfloat162 hp; hp.x = ha; hp.y = hb;
    __nv_bfloat162 lp;
    lp.x = __float2bfloat16(a - __bfloat162float(ha));
    lp.y = __float2bfloat16(b - __bfloat162float(hb));
    hi = *(unsigned*)&hp; lo = *(unsigned*)&lp;
}

// ---------------- weight prep: W[L][K][N] fp32 -> T[L][N][K] bf16 hi/lo ----------------
__global__ __launch_bounds__(256) void wprep_kernel(const float* __restrict__ W,
                             __nv_bfloat16* __restrict__ Thi,
                             __nv_bfloat16* __restrict__ Tlo,
                             int K, int N)
{
    __shared__ float tf[32][33];
    const int l = blockIdx.z;
    const int n0 = blockIdx.x*32, k0 = blockIdx.y*32;
    const int tx = threadIdx.x & 31, ty = threadIdx.x >> 5;
    const float* Wl = W + (size_t)l*K*N;
#pragma unroll
    for (int i = 0; i < 4; i++) {
        int k = k0 + ty*4 + i;
        tf[ty*4+i][tx] = Wl[(size_t)k*N + n0 + tx];
    }
    __syncthreads();
    __nv_bfloat16* Th = Thi + (size_t)l*K*N;
    __nv_bfloat16* Tl = Tlo + (size_t)l*K*N;
#pragma unroll
    for (int i = 0; i < 4; i++) {
        int n = n0 + ty*4 + i;
        float v = tf[tx][ty*4+i];
        __nv_bfloat16 h, lo; split_bf16(v, h, lo);
        Th[(size_t)n*K + k0 + tx] = h;
        Tl[(size_t)n*K + k0 + tx] = lo;
    }
}

// ---------------- mma.sync split-bf16 GEMM, CTA 128x256, warp tile 64x64 ----------------
// C[M,N] = A[M,K] @ B^T ; A as hi/lo [M,K], B as hi/lo [N,K].
// EPI: 1 +bias fp32; 2 +bias+relu bf16-pair; 3 bf16-pair (no bias).
template<int EPI>
__global__ __launch_bounds__(256, 1) void mma_gemm_kernel(
    const __nv_bfloat16* __restrict__ Ahi, const __nv_bfloat16* __restrict__ Alo,
    const __nv_bfloat16* __restrict__ Bhi, const __nv_bfloat16* __restrict__ Blo,
    const float* __restrict__ bias,
    float* __restrict__ Cf,
    __nv_bfloat16* __restrict__ Chi, __nv_bfloat16* __restrict__ Clo,
    int N, int K)
{
    extern __shared__ char smem[];
    const unsigned sbase = smem_u32(smem);
    const int tid = threadIdx.x;
    const int wid = tid >> 5, lane = tid & 31;
    const int wr = wid & 1;           // warp row: 2 x 64 rows
    const int wc = wid >> 1;          // warp col: 4 x 64 cols
    const int bm = blockIdx.y * TM;
    const int bn = blockIdx.x * TN;

    float acc[4][8][4];
#pragma unroll
    for (int ma = 0; ma < 4; ma++)
#pragma unroll
        for (int na = 0; na < 8; na++)
#pragma unroll
            for (int j = 0; j < 4; j++) acc[ma][na][j] = 0.0f;

    const int NC = K >> 6;

    // loader lambda: A 1024 16B-vecs/matrix (4 iters), B 2048 (8 iters)
    auto prefetch = [&](int c, int buf){
        const unsigned st = sbase + buf*STAGE_BYTES;
        const int k0 = c*KC;
#pragma unroll
        for (int i = 0; i < 4; i++) {
            int id = tid + i*256;
            int r = id >> 3, g = id & 7;
            unsigned so = (unsigned)(r*144 + g*16);
            size_t ga = (size_t)(bm + r)*K + k0 + g*8;
            cp16(st + OFF_AHI + so, Ahi + ga);
            cp16(st + OFF_ALO + so, Alo + ga);
        }
#pragma unroll
        for (int i = 0; i < 8; i++) {
            int id = tid + i*256;
            int r = id >> 3, g = id & 7;
            unsigned so = (unsigned)(r*144 + g*16);
            size_t gb = (size_t)(bn + r)*K + k0 + g*8;
            cp16(st + OFF_BHI + so, Bhi + gb);
            cp16(st + OFF_BLO + so, Blo + gb);
        }
    };

    prefetch(0, 0);
    CP_COMMIT();

    for (int c = 0; c < NC; c++) {
        if (c + 1 < NC) { prefetch(c+1, (c+1)&1); CP_COMMIT(); cp_wait<1>(); }
        else            { cp_wait<0>(); }
        __syncthreads();

        const char* stg = smem + (c & 1)*STAGE_BYTES;
        const __nv_bfloat16* sAh = (const __nv_bfloat16*)(stg + OFF_AHI);
        const __nv_bfloat16* sAl = (const __nv_bfloat16*)(stg + OFF_ALO);
        const __nv_bfloat16* sBh = (const __nv_bfloat16*)(stg + OFF_BHI);
        const __nv_bfloat16* sBl = (const __nv_bfloat16*)(stg + OFF_BLO);

#pragma unroll
        for (int ks = 0; ks < 4; ks++) {
            const int kk = ks*16 + (lane & 3)*2;
            unsigned ah[4][4], al[4][4];
#pragma unroll
            for (int ma = 0; ma < 4; ma++) {
                const int r0 = wr*64 + ma*16 + (lane >> 2);
                ah[ma][0] = ld2bf(sAh + r0*PADK + kk);
                ah[ma][1] = ld2bf(sAh + (r0+8)*PADK + kk);
                ah[ma][2] = ld2bf(sAh + r0*PADK + kk + 8);
                ah[ma][3] = ld2bf(sAh + (r0+8)*PADK + kk + 8);
                al[ma][0] = ld2bf(sAl + r0*PADK + kk);
                al[ma][1] = ld2bf(sAl + (r0+8)*PADK + kk);
                al[ma][2] = ld2bf(sAl + r0*PADK + kk + 8);
                al[ma][3] = ld2bf(sAl + (r0+8)*PADK + kk + 8);
            }
            // n-atoms in pairs: 3 products x 4ma x 2na per pair
#pragma unroll
            for (int nb = 0; nb < 4; nb++) {
                unsigned bh[2][2], bl[2][2];
#pragma unroll
                for (int j = 0; j < 2; j++) {
                    const int n0 = wc*64 + (nb*2 + j)*8 + (lane >> 2);
                    bh[j][0] = ld2bf(sBh + n0*PADK + kk);
                    bh[j][1] = ld2bf(sBh + n0*PADK + kk + 8);
                    bl[j][0] = ld2bf(sBl + n0*PADK + kk);
                    bl[j][1] = ld2bf(sBl + n0*PADK + kk + 8);
                }
#pragma unroll
                for (int ma = 0; ma < 4; ma++)
#pragma unroll
                    for (int j = 0; j < 2; j++)
                        mma16816(acc[ma][nb*2+j], ah[ma], bh[j]);
#pragma unroll
                for (int ma = 0; ma < 4; ma++)
#pragma unroll
                    for (int j = 0; j < 2; j++)
                        mma16816(acc[ma][nb*2+j], ah[ma], bl[j]);
#pragma unroll
                for (int ma = 0; ma < 4; ma++)
#pragma unroll
                    for (int j = 0; j < 2; j++)
                        mma16816(acc[ma][nb*2+j], al[ma], bh[j]);
            }
        }
        __syncthreads();
    }

    constexpr bool HASBIAS = (EPI == 1 || EPI == 2);
    constexpr bool RELU    = (EPI == 2);
    constexpr bool PAIR    = (EPI == 2 || EPI == 3);
#pragma unroll
    for (int ma = 0; ma < 4; ma++) {
        const int r0 = bm + wr*64 + ma*16 + (lane >> 2);
#pragma unroll
        for (int na = 0; na < 8; na++) {
            const int cc = bn + wc*64 + na*8 + (lane & 3)*2;
            float v0 = acc[ma][na][0], v1 = acc[ma][na][1];
            float v2 = acc[ma][na][2], v3 = acc[ma][na][3];
            if (HASBIAS) {
                float2 bv = *(const float2*)(bias + cc);
                v0 += bv.x; v1 += bv.y; v2 += bv.x; v3 += bv.y;
            }
            if (RELU) {
                v0 = fmaxf(v0, 0.0f); v1 = fmaxf(v1, 0.0f);
                v2 = fmaxf(v2, 0.0f); v3 = fmaxf(v3, 0.0f);
            }
            if (PAIR) {
                unsigned hi, lo;
                split2(v0, v1, hi, lo);
                *(unsigned*)(Chi + (size_t)r0*N + cc) = hi;
                *(unsigned*)(Clo + (size_t)r0*N + cc) = lo;
                split2(v2, v3, hi, lo);
                *(unsigned*)(Chi + (size_t)(r0+8)*N + cc) = hi;
                *(unsigned*)(Clo + (size_t)(r0+8)*N + cc) = lo;
            } else {
                *(float2*)(Cf + (size_t)r0*N + cc)     = make_float2(v0, v1);
                *(float2*)(Cf + (size_t)(r0+8)*N + cc) = make_float2(v2, v3);
            }
        }
    }
}

// ---------------- V transpose: qkv pair [B,S, V@1024+h*64] -> vt [bh][dh][seq] ----------------
__global__ __launch_bounds__(256) void vtrans_kernel(
    const __nv_bfloat16* __restrict__ qhi, const __nv_bfloat16* __restrict__ qlo,
    __nv_bfloat16* __restrict__ vthi, __nv_bfloat16* __restrict__ vtlo)
{
    __shared__ __nv_bfloat16 th[64][33], tl[64][33];
    const int bh = blockIdx.z, b = bh >> 3, h = bh & 7;
    const int s0 = blockIdx.x*64, d0 = blockIdx.y*32;
    const int tx = threadIdx.x & 31, ty = threadIdx.x >> 5;
#pragma unroll
    for (int i = 0; i < 8; i++) {
        int sr = ty*8 + i;
        size_t g = (size_t)(b*SEQ + s0 + sr)*1536 + 1024 + h*64 + d0 + tx;
        th[sr][tx] = qhi[g];
        tl[sr][tx] = qlo[g];
    }
    __syncthreads();
#pragma unroll
    for (int i = 0; i < 4; i++) {
        int dr = ty*4 + i;
        size_t g = ((size_t)bh*64 + d0 + dr)*1024 + s0 + tx*2;
        __nv_bfloat162 hp, lp;
        hp.x = th[tx*2][dr]; hp.y = th[tx*2+1][dr];
        lp.x = tl[tx*2][dr]; lp.y = tl[tx*2+1][dr];
        *(__nv_bfloat162*)(vthi + g) = hp;
        *(__nv_bfloat162*)(vtlo + g) = lp;
    }
}

// ---------------- fused flash attention (split-bf16 mma, online softmax) ----------------
__global__ __launch_bounds__(256, 1) void flash_kernel(
    const __nv_bfloat16* __restrict__ qhi, const __nv_bfloat16* __restrict__ qlo,
    const __nv_bfloat16* __restrict__ vthi, const __nv_bfloat16* __restrict__ vtlo,
    const float* __restrict__ kbias,
    __nv_bfloat16* __restrict__ ohi, __nv_bfloat16* __restrict__ olo)
{
    extern __shared__ char smraw[];
    __nv_bfloat16* sm = (__nv_bfloat16*)smraw;
    const unsigned sb = smem_u32(sm);
    const int tid = threadIdx.x, wid = tid >> 5, lane = tid & 31;
    const int bh = blockIdx.y, b = bh >> 3, h = bh & 7;
    const int q0 = blockIdx.x * 128;
    const int koff = (lane & 3)*2;
    const int r_base = wid*16 + (lane >> 2);

    auto prefetch_kv = [&](int t, int s){
        const int g = tid & 7;
        const int kt0 = t*64;
#pragma unroll
        for (int i = 0; i < 2; i++) {
            int r = (tid >> 3) + i*32;
            size_t gk = (size_t)(b*SEQ + kt0 + r)*1536 + 512 + h*64 + g*8;
            cp16(sb + 2*(KS_HI(s) + r*FPAD + g*8), qhi + gk);
            cp16(sb + 2*(KS_LO(s) + r*FPAD + g*8), qlo + gk);
            size_t gv = ((size_t)bh*64 + r)*1024 + kt0 + g*8;
            cp16(sb + 2*(VS_HI(s) + r*FPAD + g*8), vthi + gv);
            cp16(sb + 2*(VS_LO(s) + r*FPAD + g*8), vtlo + gv);
        }
        if (tid >= 240) {
            int j = tid - 240;
            cp16(sb + 2*BI_F(s) + j*16, kbias + b*SEQ + kt0 + j*4);
        }
    };

    {
        const int g = tid & 7;
#pragma unroll
        for (int i = 0; i < 4; i++) {
            int r = (tid >> 3) + i*32;
            size_t gq = (size_t)(b*SEQ + q0 + r)*1536 + h*64 + g*8;
            cp16(sb + 2*(Q_HI + r*FPAD + g*8), qhi + gq);
            cp16(sb + 2*(Q_LO + r*FPAD + g*8), qlo + gq);
        }
        prefetch_kv(0, 0);
        CP_COMMIT();
    }

    float m0 = -1e30f, m1 = -1e30f, l0 = 0.0f, l1 = 0.0f;
    float acc_o[8][4];
#pragma unroll
    for (int na = 0; na < 8; na++)
#pragma unroll
        for (int j = 0; j < 4; j++) acc_o[na][j] = 0.0f;

    for (int t = 0; t < NTILE; t++) {
        if (t + 1 < NTILE) { prefetch_kv(t+1, (t+1)&1); CP_COMMIT(); cp_wait<1>(); }
        else               { cp_wait<0>(); }
        __syncthreads();
        const int s = t & 1;
        const __nv_bfloat16* Kh = sm + KS_HI(s);
        const __nv_bfloat16* Kl = sm + KS_LO(s);
        const __nv_bfloat16* Vh = sm + VS_HI(s);
        const __nv_bfloat16* Vl = sm + VS_LO(s);
        const float* bsm = (const float*)(sm + BI_F(s));

        float sc[8][4];
#pragma unroll
        for (int na = 0; na < 8; na++)
#pragma unroll
            for (int j = 0; j < 4; j++) sc[na][j] = 0.0f;

#pragma unroll
        for (int kc = 0; kc < 4; kc++) {
            const int k2 = kc*16 + koff;
            unsigned ah[4], al[4];
            ah[0] = ld2bf(sm + Q_HI + r_base*FPAD + k2);
            ah[1] = ld2bf(sm + Q_HI + (r_base+8)*FPAD + k2);
            ah[2] = ld2bf(sm + Q_HI + r_base*FPAD + k2 + 8);
            ah[3] = ld2bf(sm + Q_HI + (r_base+8)*FPAD + k2 + 8);
            al[0] = ld2bf(sm + Q_LO + r_base*FPAD + k2);
            al[1] = ld2bf(sm + Q_LO + (r_base+8)*FPAD + k2);
            al[2] = ld2bf(sm + Q_LO + r_base*FPAD + k2 + 8);
            al[3] = ld2bf(sm + Q_LO + (r_base+8)*FPAD + k2 + 8);
#pragma unroll
            for (int na = 0; na < 8; na++) {
                const int n = na*8 + (lane >> 2);
                unsigned bh2[2], bl2[2];
                bh2[0] = ld2bf(Kh + n*FPAD + k2);
                bh2[1] = ld2bf(Kh + n*FPAD + k2 + 8);
                bl2[0] = ld2bf(Kl + n*FPAD + k2);
                bl2[1] = ld2bf(Kl + n*FPAD + k2 + 8);
                mma16816(sc[na], ah, bh2);
                mma16816(sc[na], ah, bl2);
                mma16816(sc[na], al, bh2);
            }
        }

#pragma unroll
        for (int na = 0; na < 8; na++) {
            float b0 = bsm[na*8 + koff], b1 = bsm[na*8 + koff + 1];
            sc[na][0] += b0; sc[na][1] += b1;
            sc[na][2] += b0; sc[na][3] += b1;
        }

        float mx0 = -1e30f, mx1 = -1e30f;
#pragma unroll
        for (int na = 0; na < 8; na++) {
            mx0 = fmaxf(mx0, fmaxf(sc[na][0], sc[na][1]));
            mx1 = fmaxf(mx1, fmaxf(sc[na][2], sc[na][3]));
        }
        mx0 = fmaxf(mx0, __shfl_xor_sync(0xffffffffu, mx0, 1));
        mx0 = fmaxf(mx0, __shfl_xor_sync(0xffffffffu, mx0, 2));
        mx1 = fmaxf(mx1, __shfl_xor_sync(0xffffffffu, mx1, 1));
        mx1 = fmaxf(mx1, __shfl_xor_sync(0xffffffffu, mx1, 2));
        float mn0 = fmaxf(m0, mx0), mn1 = fmaxf(m1, mx1);
        float e0 = __expf(m0 - mn0), e1 = __expf(m1 - mn1);
        m0 = mn0; m1 = mn1;
        float s0 = 0.0f, s1 = 0.0f;
#pragma unroll
        for (int na = 0; na < 8; na++) {
            sc[na][0] = __expf(sc[na][0] - mn0);
            sc[na][1] = __expf(sc[na][1] - mn0);
            sc[na][2] = __expf(sc[na][2] - mn1);
            sc[na][3] = __expf(sc[na][3] - mn1);
            s0 += sc[na][0] + sc[na][1];
            s1 += sc[na][2] + sc[na][3];
        }
        s0 += __shfl_xor_sync(0xffffffffu, s0, 1);
        s0 += __shfl_xor_sync(0xffffffffu, s0, 2);
        s1 += __shfl_xor_sync(0xffffffffu, s1, 1);
        s1 += __shfl_xor_sync(0xffffffffu, s1, 2);
        l0 = l0*e0 + s0;
        l1 = l1*e1 + s1;
#pragma unroll
        for (int na = 0; na < 8; na++) {
            acc_o[na][0] *= e0; acc_o[na][1] *= e0;
            acc_o[na][2] *= e1; acc_o[na][3] *= e1;
        }

#pragma unroll
        for (int kc = 0; kc < 4; kc++) {
            unsigned ph[4], pl[4];
            split2(sc[2*kc][0],   sc[2*kc][1],   ph[0], pl[0]);
            split2(sc[2*kc][2],   sc[2*kc][3],   ph[1], pl[1]);
            split2(sc[2*kc+1][0], sc[2*kc+1][1], ph[2], pl[2]);
            split2(sc[2*kc+1][2], sc[2*kc+1][3], ph[3], pl[3]);
            const int k2 = kc*16 + koff;
#pragma unroll
            for (int na = 0; na < 8; na++) {
                const int n = na*8 + (lane >> 2);
                unsigned vh2[2], vl2[2];
                vh2[0] = ld2bf(Vh + n*FPAD + k2);
                vh2[1] = ld2bf(Vh + n*FPAD + k2 + 8);
                vl2[0] = ld2bf(Vl + n*FPAD + k2);
                vl2[1] = ld2bf(Vl + n*FPAD + k2 + 8);
                mma16816(acc_o[na], ph, vh2);
                mma16816(acc_o[na], ph, vl2);
                mma16816(acc_o[na], pl, vh2);
            }
        }
        __syncthreads();
    }

    const float inv0 = 1.0f / l0, inv1 = 1.0f / l1;
    const size_t row0 = (size_t)(b*SEQ + q0 + r_base);
#pragma unroll
    for (int na = 0; na < 8; na++) {
        const int col = h*64 + na*8 + koff;
        unsigned hi, lo;
        split2(acc_o[na][0]*inv0, acc_o[na][1]*inv0, hi, lo);
        *(unsigned*)(ohi + row0*DMODEL + col) = hi;
        *(unsigned*)(olo + row0*DMODEL + col) = lo;
        split2(acc_o[na][2]*inv1, acc_o[na][3]*inv1, hi, lo);
        *(unsigned*)(ohi + (row0+8)*DMODEL + col) = hi;
        *(unsigned*)(olo + (row0+8)*DMODEL + col) = lo;
    }
}

// ---------------- positional embedding + pair split + key-mask bias ----------------
__global__ void posembed_kernel(const float* __restrict__ xin,
                                const int* __restrict__ mask,
                                float* __restrict__ xout,
                                __nv_bfloat16* __restrict__ xhi,
                                __nv_bfloat16* __restrict__ xlo,
                                float* __restrict__ kb)
{
    int b = blockIdx.x;
    int tid = threadIdx.x;                    // 1024 threads
    __shared__ int sc[SEQ];
    int valid = (mask[b*SEQ + tid] != 0) ? 1 : 0;
    kb[b*SEQ + tid] = valid ? 0.0f : -1e30f;
    sc[tid] = valid;
    __syncthreads();
    for (int off = 1; off < SEQ; off <<= 1) {
        int v = (tid >= off) ? sc[tid - off] : 0;
        __syncthreads();
        sc[tid] += v;
        __syncthreads();
    }
    int pos = sc[tid] * valid;
    __syncthreads();
    sc[tid] = pos;
    __syncthreads();

    const float cfreq = -logf(10000.0f) / 255.0f;
    for (int it = 0; it < (SEQ*DMODEL)/SEQ; it++) {
        int idx = it*SEQ + tid;
        int s = idx >> 9;
        int j = idx & 511;
        int p = sc[s];
        size_t g = ((size_t)b*SEQ + s)*DMODEL + j;
        float add = 0.0f;
        if (p > 0) {
            float fr  = expf((float)(j & 255) * cfreq);
            float ang = (float)p * fr;
            add = (j < 256) ? sinf(ang) : cosf(ang);
        }
        float v = xin[g] + add;
        xout[g] = v;
        __nv_bfloat16 h, l; split_bf16(v, h, l);
        xhi[g] = h; xlo[g] = l;
    }
}

// ---------------- out = LN(a + r) * g + b ; warp-per-row, shfl-only ----------------
__global__ __launch_bounds__(256) void ln_kernel(
    const float* __restrict__ a, const float* __restrict__ r,
    const float* __restrict__ g, const float* __restrict__ be,
    float* __restrict__ out,
    __nv_bfloat16* __restrict__ ohi, __nv_bfloat16* __restrict__ olo)
{
    const int row = blockIdx.x*8 + (threadIdx.x >> 5);
    const int lane = threadIdx.x & 31;
    const size_t base = (size_t)row*DMODEL;
    const float4* a4 = (const float4*)(a + base);
    const float4* r4 = (const float4*)(r + base);

    float4 x[4];
    float s = 0.0f;
#pragma unroll
    for (int k = 0; k < 4; k++) {
        float4 va = a4[lane + k*32];
        float4 vr = r4[lane + k*32];
        x[k] = make_float4(va.x+vr.x, va.y+vr.y, va.z+vr.z, va.w+vr.w);
        s += x[k].x + x[k].y + x[k].z + x[k].w;
    }
#pragma unroll
    for (int o = 16; o; o >>= 1) s += __shfl_xor_sync(0xffffffffu, s, o);
    const float mu = s * (1.0f/512.0f);

    float s2 = 0.0f;
#pragma unroll
    for (int k = 0; k < 4; k++) {
        x[k].x -= mu; x[k].y -= mu; x[k].z -= mu; x[k].w -= mu;
        s2 += x[k].x*x[k].x + x[k].y*x[k].y + x[k].z*x[k].z + x[k].w*x[k].w;
    }
#pragma unroll
    for (int o = 16; o; o >>= 1) s2 += __shfl_xor_sync(0xffffffffu, s2, o);
    const float inv = rsqrtf(s2 * (1.0f/512.0f) + 1e-5f);

    const float4* g4 = (const float4*)g;
    const float4* b4 = (const float4*)be;
    float4* o4 = (float4*)(out + base);
    uint2* oh2 = (uint2*)(ohi + base);
    uint2* ol2 = (uint2*)(olo + base);
#pragma unroll
    for (int k = 0; k < 4; k++) {
        float4 gg = g4[lane + k*32];
        float4 bb = b4[lane + k*32];
        float4 o;
        o.x = x[k].x*inv*gg.x + bb.x;
        o.y = x[k].y*inv*gg.y + bb.y;
        o.z = x[k].z*inv*gg.z + bb.z;
        o.w = x[k].w*inv*gg.w + bb.w;
        o4[lane + k*32] = o;
        unsigned h0, l0, h1, l1;
        split2(o.x, o.y, h0, l0);
        split2(o.z, o.w, h1, l1);
        oh2[lane + k*32] = make_uint2(h0, h1);
        ol2[lane + k*32] = make_uint2(l0, l1);
    }
}

// ---------------- driver ----------------
extern "C" void kernel_launch(void* const* d_in, const int* in_sizes, int n_in,
                              void* d_out, int out_size)
{
    const float* x_in = (const float*)d_in[0];
    const int*   mask = (const int*)d_in[3];
    const float* Wqkv = (const float*)d_in[4];
    const float* Wfc  = (const float*)d_in[5];
    const float* bfc  = (const float*)d_in[6];
    const float* ln1g = (const float*)d_in[7];
    const float* ln1b = (const float*)d_in[8];
    const float* ln2g = (const float*)d_in[9];
    const float* ln2b = (const float*)d_in[10];
    const float* W1   = (const float*)d_in[11];
    const float* b1   = (const float*)d_in[12];
    const float* W2   = (const float*)d_in[13];
    const float* b2   = (const float*)d_in[14];

    float *px, *ptmp, *pkb;
    __nv_bfloat16 *pxhi, *pxlo, *pqh, *pql, *pvth, *pvtl, *paohi, *paolo, *pfhi, *pflo;
    __nv_bfloat16 *wqh, *wql, *wfh, *wfl, *w1h, *w1l, *w2h, *w2l;
    cudaGetSymbolAddress((void**)&px,    g_x);
    cudaGetSymbolAddress((void**)&pxhi,  g_xhi);
    cudaGetSymbolAddress((void**)&pxlo,  g_xlo);
    cudaGetSymbolAddress((void**)&pqh,   g_qkvhi);
    cudaGetSymbolAddress((void**)&pql,   g_qkvlo);
    cudaGetSymbolAddress((void**)&pvth,  g_vthi);
    cudaGetSymbolAddress((void**)&pvtl,  g_vtlo);
    cudaGetSymbolAddress((void**)&pkb,   g_kbias);
    cudaGetSymbolAddress((void**)&paohi, g_aohi);
    cudaGetSymbolAddress((void**)&paolo, g_aolo);
    cudaGetSymbolAddress((void**)&ptmp,  g_tmp);
    cudaGetSymbolAddress((void**)&pfhi,  g_fhi);
    cudaGetSymbolAddress((void**)&pflo,  g_flo);
    cudaGetSymbolAddress((void**)&wqh,   g_wqkvhi);
    cudaGetSymbolAddress((void**)&wql,   g_wqkvlo);
    cudaGetSymbolAddress((void**)&wfh,   g_wfchi);
    cudaGetSymbolAddress((void**)&wfl,   g_wfclo);
    cudaGetSymbolAddress((void**)&w1h,   g_w1hi);
    cudaGetSymbolAddress((void**)&w1l,   g_w1lo);
    cudaGetSymbolAddress((void**)&w2h,   g_w2hi);
    cudaGetSymbolAddress((void**)&w2l,   g_w2lo);

    cudaFuncSetAttribute(mma_gemm_kernel<1>, cudaFuncAttributeMaxDynamicSharedMemorySize, GEMM_SMEM);
    cudaFuncSetAttribute(mma_gemm_kernel<2>, cudaFuncAttributeMaxDynamicSharedMemorySize, GEMM_SMEM);
    cudaFuncSetAttribute(mma_gemm_kernel<3>, cudaFuncAttributeMaxDynamicSharedMemorySize, GEMM_SMEM);
    cudaFuncSetAttribute(flash_kernel, cudaFuncAttributeMaxDynamicSharedMemorySize, FLASH_SMEM);

    wprep_kernel<<<dim3(3*DMODEL/32, DMODEL/32, NLAYER), 256>>>(Wqkv, wqh, wql, DMODEL, 3*DMODEL);
    wprep_kernel<<<dim3(DMODEL/32,   DMODEL/32, NLAYER), 256>>>(Wfc,  wfh, wfl, DMODEL, DMODEL);
    wprep_kernel<<<dim3(DFF/32,      DMODEL/32, NLAYER), 256>>>(W1,   w1h, w1l, DMODEL, DFF);
    wprep_kernel<<<dim3(DMODEL/32,   DFF/32,    NLAYER), 256>>>(W2,   w2h, w2l, DFF, DMODEL);

    posembed_kernel<<<BATCH, SEQ>>>(x_in, mask, px, pxhi, pxlo, pkb);

    for (int l = 0; l < NLAYER; l++) {
        size_t oq = (size_t)l*3*DMODEL*DMODEL;
        size_t of = (size_t)l*DMODEL*DMODEL;
        size_t o1 = (size_t)l*DFF*DMODEL;
        size_t o2 = (size_t)l*DMODEL*DFF;
        // QKV -> bf16 hi/lo pair   [8192,512] x [1536,512]^T
        mma_gemm_kernel<3><<<dim3(3*DMODEL/TN, NTOK/TM), 256, GEMM_SMEM>>>(
            pxhi, pxlo, wqh + oq, wql + oq, nullptr, nullptr, pqh, pql, 3*DMODEL, DMODEL);
        vtrans_kernel<<<dim3(SEQ/64, DHEAD/32, BATCH*NHEAD), 256>>>(pqh, pql, pvth, pvtl);
        flash_kernel<<<dim3(SEQ/128, BATCH*NHEAD), 256, FLASH_SMEM>>>(
            pqh, pql, pvth, pvtl, pkb, paohi, paolo);
        // proj + bias -> fp32
        mma_gemm_kernel<1><<<dim3(DMODEL/TN, NTOK/TM), 256, GEMM_SMEM>>>(
            paohi, paolo, wfh + of, wfl + of, bfc + l*DMODEL, ptmp, nullptr, nullptr, DMODEL, DMODEL);
        ln_kernel<<<NTOK/8, 256>>>(ptmp, px, ln1g + l*DMODEL, ln1b + l*DMODEL, px, pxhi, pxlo);
        // FFN up + relu -> bf16 pair
        mma_gemm_kernel<2><<<dim3(DFF/TN, NTOK/TM), 256, GEMM_SMEM>>>(
            pxhi, pxlo, w1h + o1, w1l + o1, b1 + l*DFF, nullptr, pfhi, pflo, DFF, DMODEL);
        // FFN down + bias -> fp32
        mma_gemm_kernel<1><<<dim3(DMODEL/TN, NTOK/TM), 256, GEMM_SMEM>>>(
            pfhi, pflo, w2h + o2, w2l + o2, b2 + l*DMODEL, ptmp, nullptr, nullptr, DMODEL, DFF);
        ln_kernel<<<NTOK/8, 256>>>(ptmp, px, ln2g + l*DMODEL, ln2b + l*DMODEL, px, pxhi, pxlo);
    }

    cudaMemcpyAsync(d_out, px, (size_t)NTOK*DMODEL*sizeof(float),
                    cudaMemcpyDeviceToDevice);
}

// round 11
// speedup vs baseline: 1.1262x; 1.0798x over previous
#include <cuda_runtime.h>
#include <cuda_bf16.h>
#include <math.h>

#define BATCH  8
#define SEQ    1024
#define DMODEL 512
#define NHEAD  8
#define DHEAD  64
#define NLAYER 6
#define DFF    2048
#define NTOK   (BATCH*SEQ)

// ---- mma.sync GEMM tiling (R7 shape): CTA 128x128, KC=64, ldmatrix frags ----
#define TM 128
#define TN 128
#define KC 64
#define PADK 72                       // 72 bf16 = 144B row = 36 banks (conflict-free)
#define MAT_BYTES (128*PADK*2)        // 18432
#define STAGE_BYTES (4*MAT_BYTES)     // Ahi,Alo,Bhi,Blo = 73728
#define GEMM_SMEM (2*STAGE_BYTES)     // 147456

// ---- flash attention tiling ----
#define FPAD 72
#define NTILE 16
#define Q_HI 0
#define Q_LO 9216
#define FSTG(s) (18432 + (s)*18560)
#define KS_HI(s) (FSTG(s))
#define KS_LO(s) (FSTG(s)+4608)
#define VS_HI(s) (FSTG(s)+9216)
#define VS_LO(s) (FSTG(s)+13824)
#define BI_F(s)  (FSTG(s)+18432)
#define FLASH_SMEM (2*(18432 + 2*18560))   // 111104 bytes

// ---------------- scratch (device globals) ----------------
__device__ float g_x     [(size_t)NTOK*DMODEL];
__device__ __nv_bfloat16 g_xhi[(size_t)NTOK*DMODEL];
__device__ __nv_bfloat16 g_xlo[(size_t)NTOK*DMODEL];
__device__ __nv_bfloat16 g_qkvhi[(size_t)NTOK*3*DMODEL];
__device__ __nv_bfloat16 g_qkvlo[(size_t)NTOK*3*DMODEL];
__device__ __nv_bfloat16 g_vthi[(size_t)BATCH*NHEAD*DHEAD*SEQ];
__device__ __nv_bfloat16 g_vtlo[(size_t)BATCH*NHEAD*DHEAD*SEQ];
__device__ float g_kbias [(size_t)BATCH*SEQ];
__device__ __nv_bfloat16 g_aohi[(size_t)NTOK*DMODEL];
__device__ __nv_bfloat16 g_aolo[(size_t)NTOK*DMODEL];
__device__ float g_tmp   [(size_t)NTOK*DMODEL];
__device__ __nv_bfloat16 g_fhi[(size_t)NTOK*DFF];
__device__ __nv_bfloat16 g_flo[(size_t)NTOK*DFF];
__device__ __nv_bfloat16 g_wqkvhi[(size_t)NLAYER*3*DMODEL*DMODEL];
__device__ __nv_bfloat16 g_wqkvlo[(size_t)NLAYER*3*DMODEL*DMODEL];
__device__ __nv_bfloat16 g_wfchi [(size_t)NLAYER*DMODEL*DMODEL];
__device__ __nv_bfloat16 g_wfclo [(size_t)NLAYER*DMODEL*DMODEL];
__device__ __nv_bfloat16 g_w1hi  [(size_t)NLAYER*DFF*DMODEL];
__device__ __nv_bfloat16 g_w1lo  [(size_t)NLAYER*DFF*DMODEL];
__device__ __nv_bfloat16 g_w2hi  [(size_t)NLAYER*DMODEL*DFF];
__device__ __nv_bfloat16 g_w2lo  [(size_t)NLAYER*DMODEL*DFF];

// ---------------- helpers ----------------
__device__ __forceinline__ unsigned smem_u32(const void* p){
    unsigned a;
    asm("{ .reg .u64 t; cvta.to.shared.u64 t, %1; cvt.u32.u64 %0, t; }":"=r"(a):"l"(p));
    return a;
}
__device__ __forceinline__ void cp16(unsigned saddr, const void* g){
    asm volatile("cp.async.ca.shared.global [%0], [%1], 16;" :: "r"(saddr), "l"(g));
}
#define CP_COMMIT() asm volatile("cp.async.commit_group;" ::: "memory")
template<int N> __device__ __forceinline__ void cp_wait(){
    asm volatile("cp.async.wait_group %0;" :: "n"(N) : "memory");
}
__device__ __forceinline__ void mma16816(float* d, const unsigned* a, const unsigned* b){
    asm volatile(
        "mma.sync.aligned.m16n8k16.row.col.f32.bf16.bf16.f32 "
        "{%0,%1,%2,%3}, {%4,%5,%6,%7}, {%8,%9}, {%0,%1,%2,%3};"
        : "+f"(d[0]), "+f"(d[1]), "+f"(d[2]), "+f"(d[3])
        : "r"(a[0]), "r"(a[1]), "r"(a[2]), "r"(a[3]), "r"(b[0]), "r"(b[1]));
}
__device__ __forceinline__ void ldsm4(unsigned* r, unsigned saddr){
    asm volatile("ldmatrix.sync.aligned.m8n8.x4.shared.b16 {%0,%1,%2,%3}, [%4];"
        : "=r"(r[0]), "=r"(r[1]), "=r"(r[2]), "=r"(r[3]) : "r"(saddr));
}
__device__ __forceinline__ unsigned ld2bf(const __nv_bfloat16* p){
    return *(const unsigned*)p;
}
__device__ __forceinline__ void split_bf16(float v, __nv_bfloat16& h, __nv_bfloat16& l){
    h = __float2bfloat16(v);
    l = __float2bfloat16(v - __bfloat162float(h));
}
__device__ __forceinline__ void split2(float a, float b, unsigned& hi, unsigned& lo){
    __nv_bfloat16 ha = __float2bfloat16(a), hb = __float2bfloat16(b);
    __nv_bfloat162 hp; hp.x = ha; hp.y = hb;
    __nv_bfloat162 lp;
    lp.x = __float2bfloat16(a - __bfloat162float(ha));
    lp.y = __float2bfloat16(b - __bfloat162float(hb));
    hi = *(unsigned*)&hp; lo = *(unsigned*)&lp;
}

// ---------------- merged weight prep: all 4 tensors in ONE launch ----------------
// (single launch so the ncu capture window lands on the QKV GEMM next round)
__global__ __launch_bounds__(256) void wprep_all_kernel(
    const float* __restrict__ Wq, const float* __restrict__ Wf,
    const float* __restrict__ W1, const float* __restrict__ W2,
    __nv_bfloat16* __restrict__ qh, __nv_bfloat16* __restrict__ ql,
    __nv_bfloat16* __restrict__ fh, __nv_bfloat16* __restrict__ fl,
    __nv_bfloat16* __restrict__ w1h, __nv_bfloat16* __restrict__ w1l,
    __nv_bfloat16* __restrict__ w2h, __nv_bfloat16* __restrict__ w2l)
{
    __shared__ float tf[32][33];
    int id = blockIdx.x;
    const float* W; __nv_bfloat16 *Th, *Tl; int K, N;
    if (id < 4608)        { W = Wq; Th = qh;  Tl = ql;  K = 512;  N = 1536; }
    else if (id < 6144)   { id -= 4608;  W = Wf; Th = fh;  Tl = fl;  K = 512;  N = 512; }
    else if (id < 12288)  { id -= 6144;  W = W1; Th = w1h; Tl = w1l; K = 512;  N = 2048; }
    else                  { id -= 12288; W = W2; Th = w2h; Tl = w2l; K = 2048; N = 512; }
    const int tilesN = N >> 5, tilesK = K >> 5;
    const int l = id / (tilesN*tilesK);
    const int rem = id - l*(tilesN*tilesK);
    const int n0 = (rem % tilesN)*32, k0 = (rem / tilesN)*32;
    const int tx = threadIdx.x & 31, ty = threadIdx.x >> 5;
    const float* Wl = W + (size_t)l*K*N;
#pragma unroll
    for (int i = 0; i < 4; i++) {
        int k = k0 + ty*4 + i;
        tf[ty*4+i][tx] = Wl[(size_t)k*N + n0 + tx];
    }
    __syncthreads();
    __nv_bfloat16* Thl = Th + (size_t)l*K*N;
    __nv_bfloat16* Tll = Tl + (size_t)l*K*N;
#pragma unroll
    for (int i = 0; i < 4; i++) {
        int n = n0 + ty*4 + i;
        float v = tf[tx][ty*4+i];
        __nv_bfloat16 h, lo; split_bf16(v, h, lo);
        Thl[(size_t)n*K + k0 + tx] = h;
        Tll[(size_t)n*K + k0 + tx] = lo;
    }
}

// ---------------- mma.sync split-bf16 GEMM (R7 shape + ldmatrix) ----------------
// C[M,N] = A[M,K] @ B^T ; A as hi/lo [M,K], B as hi/lo [N,K].
// EPI: 1 +bias fp32; 2 +bias+relu bf16-pair; 3 bf16-pair (no bias).
template<int EPI>
__global__ __launch_bounds__(256, 1) void mma_gemm_kernel(
    const __nv_bfloat16* __restrict__ Ahi, const __nv_bfloat16* __restrict__ Alo,
    const __nv_bfloat16* __restrict__ Bhi, const __nv_bfloat16* __restrict__ Blo,
    const float* __restrict__ bias,
    float* __restrict__ Cf,
    __nv_bfloat16* __restrict__ Chi, __nv_bfloat16* __restrict__ Clo,
    int N, int K)
{
    extern __shared__ char smem[];
    const unsigned sbase = smem_u32(smem);
    const int tid = threadIdx.x;
    const int wid = tid >> 5, lane = tid & 31;
    const int wr = wid & 3;           // warp row 0..3  (32 rows each)
    const int wc = wid >> 2;          // warp col 0..1  (64 cols each)
    const int bm = blockIdx.y * TM;
    const int bn = blockIdx.x * TN;

    // ldmatrix per-lane base offsets (bytes within one matrix)
    const int la7  = lane & 7;
    const int la8  = (lane >> 3) & 1;
    const int la16 = lane >> 4;
    // A x4 tiles: (r0,k),(r0+8,k),(r0,k+8),(r0+8,k+8)
    const unsigned aoff = (unsigned)((wr*32 + la7 + la8*8)*PADK + la16*8) * 2u;
    // B x4 tiles: (na0,k),(na0,k+8),(na1,k),(na1,k+8) -> n-atom = g>>1, k-half = g&1
    const unsigned boff = (unsigned)((wc*64 + la16*8 + la7)*PADK + la8*8) * 2u;

    // loaders: 1024 16B-vecs per 128x64 matrix, 4 per thread
    const int lr = tid >> 3;
    const int lg = tid & 7;

    float acc[2][8][4];
#pragma unroll
    for (int ma = 0; ma < 2; ma++)
#pragma unroll
        for (int na = 0; na < 8; na++)
#pragma unroll
            for (int j = 0; j < 4; j++) acc[ma][na][j] = 0.0f;

    const int NC = K >> 6;

    {
        const unsigned st = sbase;
#pragma unroll
        for (int i = 0; i < 4; i++) {
            int r = lr + i*32;
            unsigned so = (unsigned)(r*144 + lg*16);
            size_t ga = (size_t)(bm + r)*K + lg*8;
            size_t gb = (size_t)(bn + r)*K + lg*8;
            cp16(st + so,                 Ahi + ga);
            cp16(st + MAT_BYTES + so,     Alo + ga);
            cp16(st + 2*MAT_BYTES + so,   Bhi + gb);
            cp16(st + 3*MAT_BYTES + so,   Blo + gb);
        }
        CP_COMMIT();
    }

    for (int c = 0; c < NC; c++) {
        if (c + 1 < NC) {
            const unsigned st = sbase + ((c+1) & 1)*STAGE_BYTES;
            const int k0 = (c+1)*KC;
#pragma unroll
            for (int i = 0; i < 4; i++) {
                int r = lr + i*32;
                unsigned so = (unsigned)(r*144 + lg*16);
                size_t ga = (size_t)(bm + r)*K + k0 + lg*8;
                size_t gb = (size_t)(bn + r)*K + k0 + lg*8;
                cp16(st + so,                 Ahi + ga);
                cp16(st + MAT_BYTES + so,     Alo + ga);
                cp16(st + 2*MAT_BYTES + so,   Bhi + gb);
                cp16(st + 3*MAT_BYTES + so,   Blo + gb);
            }
            CP_COMMIT();
            cp_wait<1>();
        } else {
            cp_wait<0>();
        }
        __syncthreads();

        const unsigned stg = sbase + (c & 1)*STAGE_BYTES;
        const unsigned sAh = stg + aoff;
        const unsigned sAl = stg + MAT_BYTES + aoff;
        const unsigned sBh = stg + 2*MAT_BYTES + boff;
        const unsigned sBl = stg + 3*MAT_BYTES + boff;

#pragma unroll
        for (int ks = 0; ks < 4; ks++) {
            const unsigned kb = (unsigned)(ks*32);   // 16 elements * 2B
            unsigned ah[2][4], al[2][4];
#pragma unroll
            for (int ma = 0; ma < 2; ma++) {
                ldsm4(ah[ma], sAh + (unsigned)(ma*16*PADK*2) + kb);
                ldsm4(al[ma], sAl + (unsigned)(ma*16*PADK*2) + kb);
            }
            unsigned bh[4][4], bl[4][4];
#pragma unroll
            for (int nb = 0; nb < 4; nb++) {
                ldsm4(bh[nb], sBh + (unsigned)(nb*16*PADK*2) + kb);
                ldsm4(bl[nb], sBl + (unsigned)(nb*16*PADK*2) + kb);
            }
            // product 1: Ahi * Bhi
#pragma unroll
            for (int ma = 0; ma < 2; ma++)
#pragma unroll
                for (int na = 0; na < 8; na++)
                    mma16816(acc[ma][na], ah[ma], &bh[na>>1][(na&1)*2]);
            // product 2: Ahi * Blo
#pragma unroll
            for (int ma = 0; ma < 2; ma++)
#pragma unroll
                for (int na = 0; na < 8; na++)
                    mma16816(acc[ma][na], ah[ma], &bl[na>>1][(na&1)*2]);
            // product 3: Alo * Bhi
#pragma unroll
            for (int ma = 0; ma < 2; ma++)
#pragma unroll
                for (int na = 0; na < 8; na++)
                    mma16816(acc[ma][na], al[ma], &bh[na>>1][(na&1)*2]);
        }
        __syncthreads();
    }

    constexpr bool HASBIAS = (EPI == 1 || EPI == 2);
    constexpr bool RELU    = (EPI == 2);
    constexpr bool PAIR    = (EPI == 2 || EPI == 3);
#pragma unroll
    for (int ma = 0; ma < 2; ma++) {
        const int r0 = bm + wr*32 + ma*16 + (lane >> 2);
#pragma unroll
        for (int na = 0; na < 8; na++) {
            const int cc = bn + wc*64 + na*8 + (lane & 3)*2;
            float v0 = acc[ma][na][0], v1 = acc[ma][na][1];
            float v2 = acc[ma][na][2], v3 = acc[ma][na][3];
            if (HASBIAS) {
                float2 bv = *(const float2*)(bias + cc);
                v0 += bv.x; v1 += bv.y; v2 += bv.x; v3 += bv.y;
            }
            if (RELU) {
                v0 = fmaxf(v0, 0.0f); v1 = fmaxf(v1, 0.0f);
                v2 = fmaxf(v2, 0.0f); v3 = fmaxf(v3, 0.0f);
            }
            if (PAIR) {
                unsigned hi, lo;
                split2(v0, v1, hi, lo);
                *(unsigned*)(Chi + (size_t)r0*N + cc) = hi;
                *(unsigned*)(Clo + (size_t)r0*N + cc) = lo;
                split2(v2, v3, hi, lo);
                *(unsigned*)(Chi + (size_t)(r0+8)*N + cc) = hi;
                *(unsigned*)(Clo + (size_t)(r0+8)*N + cc) = lo;
            } else {
                *(float2*)(Cf + (size_t)r0*N + cc)     = make_float2(v0, v1);
                *(float2*)(Cf + (size_t)(r0+8)*N + cc) = make_float2(v2, v3);
            }
        }
    }
}

// ---------------- V transpose: qkv pair [B,S, V@1024+h*64] -> vt [bh][dh][seq] ----------------
__global__ __launch_bounds__(256) void vtrans_kernel(
    const __nv_bfloat16* __restrict__ qhi, const __nv_bfloat16* __restrict__ qlo,
    __nv_bfloat16* __restrict__ vthi, __nv_bfloat16* __restrict__ vtlo)
{
    __shared__ __nv_bfloat16 th[64][33], tl[64][33];
    const int bh = blockIdx.z, b = bh >> 3, h = bh & 7;
    const int s0 = blockIdx.x*64, d0 = blockIdx.y*32;
    const int tx = threadIdx.x & 31, ty = threadIdx.x >> 5;
#pragma unroll
    for (int i = 0; i < 8; i++) {
        int sr = ty*8 + i;
        size_t g = (size_t)(b*SEQ + s0 + sr)*1536 + 1024 + h*64 + d0 + tx;
        th[sr][tx] = qhi[g];
        tl[sr][tx] = qlo[g];
    }
    __syncthreads();
#pragma unroll
    for (int i = 0; i < 4; i++) {
        int dr = ty*4 + i;
        size_t g = ((size_t)bh*64 + d0 + dr)*1024 + s0 + tx*2;
        __nv_bfloat162 hp, lp;
        hp.x = th[tx*2][dr]; hp.y = th[tx*2+1][dr];
        lp.x = tl[tx*2][dr]; lp.y = tl[tx*2+1][dr];
        *(__nv_bfloat162*)(vthi + g) = hp;
        *(__nv_bfloat162*)(vtlo + g) = lp;
    }
}

// ---------------- fused flash attention (split-bf16 mma, online softmax) ----------------
__global__ __launch_bounds__(256, 1) void flash_kernel(
    const __nv_bfloat16* __restrict__ qhi, const __nv_bfloat16* __restrict__ qlo,
    const __nv_bfloat16* __restrict__ vthi, const __nv_bfloat16* __restrict__ vtlo,
    const float* __restrict__ kbias,
    __nv_bfloat16* __restrict__ ohi, __nv_bfloat16* __restrict__ olo)
{
    extern __shared__ char smraw[];
    __nv_bfloat16* sm = (__nv_bfloat16*)smraw;
    const unsigned sb = smem_u32(sm);
    const int tid = threadIdx.x, wid = tid >> 5, lane = tid & 31;
    const int bh = blockIdx.y, b = bh >> 3, h = bh & 7;
    const int q0 = blockIdx.x * 128;
    const int koff = (lane & 3)*2;
    const int r_base = wid*16 + (lane >> 2);

    auto prefetch_kv = [&](int t, int s){
        const int g = tid & 7;
        const int kt0 = t*64;
#pragma unroll
        for (int i = 0; i < 2; i++) {
            int r = (tid >> 3) + i*32;
            size_t gk = (size_t)(b*SEQ + kt0 + r)*1536 + 512 + h*64 + g*8;
            cp16(sb + 2*(KS_HI(s) + r*FPAD + g*8), qhi + gk);
            cp16(sb + 2*(KS_LO(s) + r*FPAD + g*8), qlo + gk);
            size_t gv = ((size_t)bh*64 + r)*1024 + kt0 + g*8;
            cp16(sb + 2*(VS_HI(s) + r*FPAD + g*8), vthi + gv);
            cp16(sb + 2*(VS_LO(s) + r*FPAD + g*8), vtlo + gv);
        }
        if (tid >= 240) {
            int j = tid - 240;
            cp16(sb + 2*BI_F(s) + j*16, kbias + b*SEQ + kt0 + j*4);
        }
    };

    {
        const int g = tid & 7;
#pragma unroll
        for (int i = 0; i < 4; i++) {
            int r = (tid >> 3) + i*32;
            size_t gq = (size_t)(b*SEQ + q0 + r)*1536 + h*64 + g*8;
            cp16(sb + 2*(Q_HI + r*FPAD + g*8), qhi + gq);
            cp16(sb + 2*(Q_LO + r*FPAD + g*8), qlo + gq);
        }
        prefetch_kv(0, 0);
        CP_COMMIT();
    }

    float m0 = -1e30f, m1 = -1e30f, l0 = 0.0f, l1 = 0.0f;
    float acc_o[8][4];
#pragma unroll
    for (int na = 0; na < 8; na++)
#pragma unroll
        for (int j = 0; j < 4; j++) acc_o[na][j] = 0.0f;

    for (int t = 0; t < NTILE; t++) {
        if (t + 1 < NTILE) { prefetch_kv(t+1, (t+1)&1); CP_COMMIT(); cp_wait<1>(); }
        else               { cp_wait<0>(); }
        __syncthreads();
        const int s = t & 1;
        const __nv_bfloat16* Kh = sm + KS_HI(s);
        const __nv_bfloat16* Kl = sm + KS_LO(s);
        const __nv_bfloat16* Vh = sm + VS_HI(s);
        const __nv_bfloat16* Vl = sm + VS_LO(s);
        const float* bsm = (const float*)(sm + BI_F(s));

        float sc[8][4];
#pragma unroll
        for (int na = 0; na < 8; na++)
#pragma unroll
            for (int j = 0; j < 4; j++) sc[na][j] = 0.0f;

#pragma unroll
        for (int kc = 0; kc < 4; kc++) {
            const int k2 = kc*16 + koff;
            unsigned ah[4], al[4];
            ah[0] = ld2bf(sm + Q_HI + r_base*FPAD + k2);
            ah[1] = ld2bf(sm + Q_HI + (r_base+8)*FPAD + k2);
            ah[2] = ld2bf(sm + Q_HI + r_base*FPAD + k2 + 8);
            ah[3] = ld2bf(sm + Q_HI + (r_base+8)*FPAD + k2 + 8);
            al[0] = ld2bf(sm + Q_LO + r_base*FPAD + k2);
            al[1] = ld2bf(sm + Q_LO + (r_base+8)*FPAD + k2);
            al[2] = ld2bf(sm + Q_LO + r_base*FPAD + k2 + 8);
            al[3] = ld2bf(sm + Q_LO + (r_base+8)*FPAD + k2 + 8);
#pragma unroll
            for (int na = 0; na < 8; na++) {
                const int n = na*8 + (lane >> 2);
                unsigned bh2[2], bl2[2];
                bh2[0] = ld2bf(Kh + n*FPAD + k2);
                bh2[1] = ld2bf(Kh + n*FPAD + k2 + 8);
                bl2[0] = ld2bf(Kl + n*FPAD + k2);
                bl2[1] = ld2bf(Kl + n*FPAD + k2 + 8);
                mma16816(sc[na], ah, bh2);
                mma16816(sc[na], ah, bl2);
                mma16816(sc[na], al, bh2);
            }
        }

#pragma unroll
        for (int na = 0; na < 8; na++) {
            float b0 = bsm[na*8 + koff], b1 = bsm[na*8 + koff + 1];
            sc[na][0] += b0; sc[na][1] += b1;
            sc[na][2] += b0; sc[na][3] += b1;
        }

        float mx0 = -1e30f, mx1 = -1e30f;
#pragma unroll
        for (int na = 0; na < 8; na++) {
            mx0 = fmaxf(mx0, fmaxf(sc[na][0], sc[na][1]));
            mx1 = fmaxf(mx1, fmaxf(sc[na][2], sc[na][3]));
        }
        mx0 = fmaxf(mx0, __shfl_xor_sync(0xffffffffu, mx0, 1));
        mx0 = fmaxf(mx0, __shfl_xor_sync(0xffffffffu, mx0, 2));
        mx1 = fmaxf(mx1, __shfl_xor_sync(0xffffffffu, mx1, 1));
        mx1 = fmaxf(mx1, __shfl_xor_sync(0xffffffffu, mx1, 2));
        float mn0 = fmaxf(m0, mx0), mn1 = fmaxf(m1, mx1);
        float e0 = __expf(m0 - mn0), e1 = __expf(m1 - mn1);
        m0 = mn0; m1 = mn1;
        float s0 = 0.0f, s1 = 0.0f;
#pragma unroll
        for (int na = 0; na < 8; na++) {
            sc[na][0] = __expf(sc[na][0] - mn0);
            sc[na][1] = __expf(sc[na][1] - mn0);
            sc[na][2] = __expf(sc[na][2] - mn1);
            sc[na][3] = __expf(sc[na][3] - mn1);
            s0 += sc[na][0] + sc[na][1];
            s1 += sc[na][2] + sc[na][3];
        }
        s0 += __shfl_xor_sync(0xffffffffu, s0, 1);
        s0 += __shfl_xor_sync(0xffffffffu, s0, 2);
        s1 += __shfl_xor_sync(0xffffffffu, s1, 1);
        s1 += __shfl_xor_sync(0xffffffffu, s1, 2);
        l0 = l0*e0 + s0;
        l1 = l1*e1 + s1;
#pragma unroll
        for (int na = 0; na < 8; na++) {
            acc_o[na][0] *= e0; acc_o[na][1] *= e0;
            acc_o[na][2] *= e1; acc_o[na][3] *= e1;
        }

#pragma unroll
        for (int kc = 0; kc < 4; kc++) {
            unsigned ph[4], pl[4];
            split2(sc[2*kc][0],   sc[2*kc][1],   ph[0], pl[0]);
            split2(sc[2*kc][2],   sc[2*kc][3],   ph[1], pl[1]);
            split2(sc[2*kc+1][0], sc[2*kc+1][1], ph[2], pl[2]);
            split2(sc[2*kc+1][2], sc[2*kc+1][3], ph[3], pl[3]);
            const int k2 = kc*16 + koff;
#pragma unroll
            for (int na = 0; na < 8; na++) {
                const int n = na*8 + (lane >> 2);
                unsigned vh2[2], vl2[2];
                vh2[0] = ld2bf(Vh + n*FPAD + k2);
                vh2[1] = ld2bf(Vh + n*FPAD + k2 + 8);
                vl2[0] = ld2bf(Vl + n*FPAD + k2);
                vl2[1] = ld2bf(Vl + n*FPAD + k2 + 8);
                mma16816(acc_o[na], ph, vh2);
                mma16816(acc_o[na], ph, vl2);
                mma16816(acc_o[na], pl, vh2);
            }
        }
        __syncthreads();
    }

    const float inv0 = 1.0f / l0, inv1 = 1.0f / l1;
    const size_t row0 = (size_t)(b*SEQ + q0 + r_base);
#pragma unroll
    for (int na = 0; na < 8; na++) {
        const int col = h*64 + na*8 + koff;
        unsigned hi, lo;
        split2(acc_o[na][0]*inv0, acc_o[na][1]*inv0, hi, lo);
        *(unsigned*)(ohi + row0*DMODEL + col) = hi;
        *(unsigned*)(olo + row0*DMODEL + col) = lo;
        split2(acc_o[na][2]*inv1, acc_o[na][3]*inv1, hi, lo);
        *(unsigned*)(ohi + (row0+8)*DMODEL + col) = hi;
        *(unsigned*)(olo + (row0+8)*DMODEL + col) = lo;
    }
}

// ---------------- positional embedding + pair split + key-mask bias ----------------
__global__ void posembed_kernel(const float* __restrict__ xin,
                                const int* __restrict__ mask,
                                float* __restrict__ xout,
                                __nv_bfloat16* __restrict__ xhi,
                                __nv_bfloat16* __restrict__ xlo,
                                float* __restrict__ kb)
{
    int b = blockIdx.x;
    int tid = threadIdx.x;                    // 1024 threads
    __shared__ int sc[SEQ];
    int valid = (mask[b*SEQ + tid] != 0) ? 1 : 0;
    kb[b*SEQ + tid] = valid ? 0.0f : -1e30f;
    sc[tid] = valid;
    __syncthreads();
    for (int off = 1; off < SEQ; off <<= 1) {
        int v = (tid >= off) ? sc[tid - off] : 0;
        __syncthreads();
        sc[tid] += v;
        __syncthreads();
    }
    int pos = sc[tid] * valid;
    __syncthreads();
    sc[tid] = pos;
    __syncthreads();

    const float cfreq = -logf(10000.0f) / 255.0f;
    for (int it = 0; it < (SEQ*DMODEL)/SEQ; it++) {
        int idx = it*SEQ + tid;
        int s = idx >> 9;
        int j = idx & 511;
        int p = sc[s];
        size_t g = ((size_t)b*SEQ + s)*DMODEL + j;
        float add = 0.0f;
        if (p > 0) {
            float fr  = expf((float)(j & 255) * cfreq);
            float ang = (float)p * fr;
            add = (j < 256) ? sinf(ang) : cosf(ang);
        }
        float v = xin[g] + add;
        xout[g] = v;
        __nv_bfloat16 h, l; split_bf16(v, h, l);
        xhi[g] = h; xlo[g] = l;
    }
}

// ---------------- out = LN(a + r) * g + b ; warp-per-row, shfl-only ----------------
__global__ __launch_bounds__(256) void ln_kernel(
    const float* __restrict__ a, const float* __restrict__ r,
    const float* __restrict__ g, const float* __restrict__ be,
    float* __restrict__ out,
    __nv_bfloat16* __restrict__ ohi, __nv_bfloat16* __restrict__ olo)
{
    const int row = blockIdx.x*8 + (threadIdx.x >> 5);
    const int lane = threadIdx.x & 31;
    const size_t base = (size_t)row*DMODEL;
    const float4* a4 = (const float4*)(a + base);
    const float4* r4 = (const float4*)(r + base);

    float4 x[4];
    float s = 0.0f;
#pragma unroll
    for (int k = 0; k < 4; k++) {
        float4 va = a4[lane + k*32];
        float4 vr = r4[lane + k*32];
        x[k] = make_float4(va.x+vr.x, va.y+vr.y, va.z+vr.z, va.w+vr.w);
        s += x[k].x + x[k].y + x[k].z + x[k].w;
    }
#pragma unroll
    for (int o = 16; o; o >>= 1) s += __shfl_xor_sync(0xffffffffu, s, o);
    const float mu = s * (1.0f/512.0f);

    float s2 = 0.0f;
#pragma unroll
    for (int k = 0; k < 4; k++) {
        x[k].x -= mu; x[k].y -= mu; x[k].z -= mu; x[k].w -= mu;
        s2 += x[k].x*x[k].x + x[k].y*x[k].y + x[k].z*x[k].z + x[k].w*x[k].w;
    }
#pragma unroll
    for (int o = 16; o; o >>= 1) s2 += __shfl_xor_sync(0xffffffffu, s2, o);
    const float inv = rsqrtf(s2 * (1.0f/512.0f) + 1e-5f);

    const float4* g4 = (const float4*)g;
    const float4* b4 = (const float4*)be;
    float4* o4 = (float4*)(out + base);
    uint2* oh2 = (uint2*)(ohi + base);
    uint2* ol2 = (uint2*)(olo + base);
#pragma unroll
    for (int k = 0; k < 4; k++) {
        float4 gg = g4[lane + k*32];
        float4 bb = b4[lane + k*32];
        float4 o;
        o.x = x[k].x*inv*gg.x + bb.x;
        o.y = x[k].y*inv*gg.y + bb.y;
        o.z = x[k].z*inv*gg.z + bb.z;
        o.w = x[k].w*inv*gg.w + bb.w;
        o4[lane + k*32] = o;
        unsigned h0, l0, h1, l1;
        split2(o.x, o.y, h0, l0);
        split2(o.z, o.w, h1, l1);
        oh2[lane + k*32] = make_uint2(h0, h1);
        ol2[lane + k*32] = make_uint2(l0, l1);
    }
}

// ---------------- driver ----------------
extern "C" void kernel_launch(void* const* d_in, const int* in_sizes, int n_in,
                              void* d_out, int out_size)
{
    const float* x_in = (const float*)d_in[0];
    const int*   mask = (const int*)d_in[3];
    const float* Wqkv = (const float*)d_in[4];
    const float* Wfc  = (const float*)d_in[5];
    const float* bfc  = (const float*)d_in[6];
    const float* ln1g = (const float*)d_in[7];
    const float* ln1b = (const float*)d_in[8];
    const float* ln2g = (const float*)d_in[9];
    const float* ln2b = (const float*)d_in[10];
    const float* W1   = (const float*)d_in[11];
    const float* b1   = (const float*)d_in[12];
    const float* W2   = (const float*)d_in[13];
    const float* b2   = (const float*)d_in[14];

    float *px, *ptmp, *pkb;
    __nv_bfloat16 *pxhi, *pxlo, *pqh, *pql, *pvth, *pvtl, *paohi, *paolo, *pfhi, *pflo;
    __nv_bfloat16 *wqh, *wql, *wfh, *wfl, *w1h, *w1l, *w2h, *w2l;
    cudaGetSymbolAddress((void**)&px,    g_x);
    cudaGetSymbolAddress((void**)&pxhi,  g_xhi);
    cudaGetSymbolAddress((void**)&pxlo,  g_xlo);
    cudaGetSymbolAddress((void**)&pqh,   g_qkvhi);
    cudaGetSymbolAddress((void**)&pql,   g_qkvlo);
    cudaGetSymbolAddress((void**)&pvth,  g_vthi);
    cudaGetSymbolAddress((void**)&pvtl,  g_vtlo);
    cudaGetSymbolAddress((void**)&pkb,   g_kbias);
    cudaGetSymbolAddress((void**)&paohi, g_aohi);
    cudaGetSymbolAddress((void**)&paolo, g_aolo);
    cudaGetSymbolAddress((void**)&ptmp,  g_tmp);
    cudaGetSymbolAddress((void**)&pfhi,  g_fhi);
    cudaGetSymbolAddress((void**)&pflo,  g_flo);
    cudaGetSymbolAddress((void**)&wqh,   g_wqkvhi);
    cudaGetSymbolAddress((void**)&wql,   g_wqkvlo);
    cudaGetSymbolAddress((void**)&wfh,   g_wfchi);
    cudaGetSymbolAddress((void**)&wfl,   g_wfclo);
    cudaGetSymbolAddress((void**)&w1h,   g_w1hi);
    cudaGetSymbolAddress((void**)&w1l,   g_w1lo);
    cudaGetSymbolAddress((void**)&w2h,   g_w2hi);
    cudaGetSymbolAddress((void**)&w2l,   g_w2lo);

    cudaFuncSetAttribute(mma_gemm_kernel<1>, cudaFuncAttributeMaxDynamicSharedMemorySize, GEMM_SMEM);
    cudaFuncSetAttribute(mma_gemm_kernel<2>, cudaFuncAttributeMaxDynamicSharedMemorySize, GEMM_SMEM);
    cudaFuncSetAttribute(mma_gemm_kernel<3>, cudaFuncAttributeMaxDynamicSharedMemorySize, GEMM_SMEM);
    cudaFuncSetAttribute(flash_kernel, cudaFuncAttributeMaxDynamicSharedMemorySize, FLASH_SMEM);

    // single merged weight-prep launch (also steers ncu capture onto the QKV GEMM)
    wprep_all_kernel<<<18432, 256>>>(Wqkv, Wfc, W1, W2,
                                     wqh, wql, wfh, wfl, w1h, w1l, w2h, w2l);

    posembed_kernel<<<BATCH, SEQ>>>(x_in, mask, px, pxhi, pxlo, pkb);

    for (int l = 0; l < NLAYER; l++) {
        size_t oq = (size_t)l*3*DMODEL*DMODEL;
        size_t of = (size_t)l*DMODEL*DMODEL;
        size_t o1 = (size_t)l*DFF*DMODEL;
        size_t o2 = (size_t)l*DMODEL*DFF;
        // QKV -> bf16 hi/lo pair   [8192,512] x [1536,512]^T
        mma_gemm_kernel<3><<<dim3(3*DMODEL/TN, NTOK/TM), 256, GEMM_SMEM>>>(
            pxhi, pxlo, wqh + oq, wql + oq, nullptr, nullptr, pqh, pql, 3*DMODEL, DMODEL);
        vtrans_kernel<<<dim3(SEQ/64, DHEAD/32, BATCH*NHEAD), 256>>>(pqh, pql, pvth, pvtl);
        flash_kernel<<<dim3(SEQ/128, BATCH*NHEAD), 256, FLASH_SMEM>>>(
            pqh, pql, pvth, pvtl, pkb, paohi, paolo);
        // proj + bias -> fp32
        mma_gemm_kernel<1><<<dim3(DMODEL/TN, NTOK/TM), 256, GEMM_SMEM>>>(
            paohi, paolo, wfh + of, wfl + of, bfc + l*DMODEL, ptmp, nullptr, nullptr, DMODEL, DMODEL);
        ln_kernel<<<NTOK/8, 256>>>(ptmp, px, ln1g + l*DMODEL, ln1b + l*DMODEL, px, pxhi, pxlo);
        // FFN up + relu -> bf16 pair
        mma_gemm_kernel<2><<<dim3(DFF/TN, NTOK/TM), 256, GEMM_SMEM>>>(
            pxhi, pxlo, w1h + o1, w1l + o1, b1 + l*DFF, nullptr, pfhi, pflo, DFF, DMODEL);
        // FFN down + bias -> fp32
        mma_gemm_kernel<1><<<dim3(DMODEL/TN, NTOK/TM), 256, GEMM_SMEM>>>(
            pfhi, pflo, w2h + o2, w2l + o2, b2 + l*DMODEL, ptmp, nullptr, nullptr, DMODEL, DFF);
        ln_kernel<<<NTOK/8, 256>>>(ptmp, px, ln2g + l*DMODEL, ln2b + l*DMODEL, px, pxhi, pxlo);
    }

    cudaMemcpyAsync(d_out, px, (size_t)NTOK*DMODEL*sizeof(float),
                    cudaMemcpyDeviceToDevice);
}

// round 12
// speedup vs baseline: 1.1434x; 1.0152x over previous
#include <cuda_runtime.h>
#include <cuda_bf16.h>
#include <math.h>

#define BATCH  8
#define SEQ    1024
#define DMODEL 512
#define NHEAD  8
#define DHEAD  64
#define NLAYER 6
#define DFF    2048
#define NTOK   (BATCH*SEQ)

// ---- mma.sync GEMM tiling (R10/R11 proven): CTA 128x128, KC=64, ldmatrix ----
#define TM 128
#define TN 128
#define KC 64
#define PADK 72                       // 72 bf16 = 144B row (16B-aligned, conflict-free)
#define MAT_BYTES (128*PADK*2)        // 18432
#define STAGE_BYTES (4*MAT_BYTES)     // 73728
#define GEMM_SMEM (2*STAGE_BYTES)     // 147456

// ---- flash attention tiling ----
#define FPAD 72
#define NTILE 16
// bf16-element offsets in dynamic smem
#define Q_HI 0
#define Q_LO 9216
#define FSTG(s) (18432 + (s)*18560)
#define KS_HI(s) (FSTG(s))
#define KS_LO(s) (FSTG(s)+4608)
#define VS_HI(s) (FSTG(s)+9216)
#define VS_LO(s) (FSTG(s)+13824)
#define BI_F(s)  (FSTG(s)+18432)
#define FLASH_SMEM (2*(18432 + 2*18560))   // 111104 bytes

// ---------------- scratch (device globals) ----------------
__device__ float g_x     [(size_t)NTOK*DMODEL];
__device__ __nv_bfloat16 g_xhi[(size_t)NTOK*DMODEL];
__device__ __nv_bfloat16 g_xlo[(size_t)NTOK*DMODEL];
__device__ __nv_bfloat16 g_qkvhi[(size_t)NTOK*3*DMODEL];
__device__ __nv_bfloat16 g_qkvlo[(size_t)NTOK*3*DMODEL];
__device__ float g_kbias [(size_t)BATCH*SEQ];
__device__ __nv_bfloat16 g_aohi[(size_t)NTOK*DMODEL];
__device__ __nv_bfloat16 g_aolo[(size_t)NTOK*DMODEL];
__device__ float g_tmp   [(size_t)NTOK*DMODEL];
__device__ __nv_bfloat16 g_fhi[(size_t)NTOK*DFF];
__device__ __nv_bfloat16 g_flo[(size_t)NTOK*DFF];
__device__ __nv_bfloat16 g_wqkvhi[(size_t)NLAYER*3*DMODEL*DMODEL];
__device__ __nv_bfloat16 g_wqkvlo[(size_t)NLAYER*3*DMODEL*DMODEL];
__device__ __nv_bfloat16 g_wfchi [(size_t)NLAYER*DMODEL*DMODEL];
__device__ __nv_bfloat16 g_wfclo [(size_t)NLAYER*DMODEL*DMODEL];
__device__ __nv_bfloat16 g_w1hi  [(size_t)NLAYER*DFF*DMODEL];
__device__ __nv_bfloat16 g_w1lo  [(size_t)NLAYER*DFF*DMODEL];
__device__ __nv_bfloat16 g_w2hi  [(size_t)NLAYER*DMODEL*DFF];
__device__ __nv_bfloat16 g_w2lo  [(size_t)NLAYER*DMODEL*DFF];

// ---------------- helpers ----------------
__device__ __forceinline__ unsigned smem_u32(const void* p){
    unsigned a;
    asm("{ .reg .u64 t; cvta.to.shared.u64 t, %1; cvt.u32.u64 %0, t; }":"=r"(a):"l"(p));
    return a;
}
__device__ __forceinline__ void cp16(unsigned saddr, const void* g){
    asm volatile("cp.async.ca.shared.global [%0], [%1], 16;" :: "r"(saddr), "l"(g));
}
#define CP_COMMIT() asm volatile("cp.async.commit_group;" ::: "memory")
template<int N> __device__ __forceinline__ void cp_wait(){
    asm volatile("cp.async.wait_group %0;" :: "n"(N) : "memory");
}
__device__ __forceinline__ void mma16816(float* d, const unsigned* a, const unsigned* b){
    asm volatile(
        "mma.sync.aligned.m16n8k16.row.col.f32.bf16.bf16.f32 "
        "{%0,%1,%2,%3}, {%4,%5,%6,%7}, {%8,%9}, {%0,%1,%2,%3};"
        : "+f"(d[0]), "+f"(d[1]), "+f"(d[2]), "+f"(d[3])
        : "r"(a[0]), "r"(a[1]), "r"(a[2]), "r"(a[3]), "r"(b[0]), "r"(b[1]));
}
__device__ __forceinline__ void ldsm4(unsigned* r, unsigned saddr){
    asm volatile("ldmatrix.sync.aligned.m8n8.x4.shared.b16 {%0,%1,%2,%3}, [%4];"
        : "=r"(r[0]), "=r"(r[1]), "=r"(r[2]), "=r"(r[3]) : "r"(saddr));
}
__device__ __forceinline__ void ldsm4t(unsigned* r, unsigned saddr){
    asm volatile("ldmatrix.sync.aligned.m8n8.x4.trans.shared.b16 {%0,%1,%2,%3}, [%4];"
        : "=r"(r[0]), "=r"(r[1]), "=r"(r[2]), "=r"(r[3]) : "r"(saddr));
}
__device__ __forceinline__ void split_bf16(float v, __nv_bfloat16& h, __nv_bfloat16& l){
    h = __float2bfloat16(v);
    l = __float2bfloat16(v - __bfloat162float(h));
}
__device__ __forceinline__ void split2(float a, float b, unsigned& hi, unsigned& lo){
    __nv_bfloat16 ha = __float2bfloat16(a), hb = __float2bfloat16(b);
    __nv_bfloat162 hp; hp.x = ha; hp.y = hb;
    __nv_bfloat162 lp;
    lp.x = __float2bfloat16(a - __bfloat162float(ha));
    lp.y = __float2bfloat16(b - __bfloat162float(hb));
    hi = *(unsigned*)&hp; lo = *(unsigned*)&lp;
}

// ---------------- merged weight prep: all 4 tensors in ONE launch ----------------
__global__ __launch_bounds__(256) void wprep_all_kernel(
    const float* __restrict__ Wq, const float* __restrict__ Wf,
    const float* __restrict__ W1, const float* __restrict__ W2,
    __nv_bfloat16* __restrict__ qh, __nv_bfloat16* __restrict__ ql,
    __nv_bfloat16* __restrict__ fh, __nv_bfloat16* __restrict__ fl,
    __nv_bfloat16* __restrict__ w1h, __nv_bfloat16* __restrict__ w1l,
    __nv_bfloat16* __restrict__ w2h, __nv_bfloat16* __restrict__ w2l)
{
    __shared__ float tf[32][33];
    int id = blockIdx.x;
    const float* W; __nv_bfloat16 *Th, *Tl; int K, N;
    if (id < 4608)        { W = Wq; Th = qh;  Tl = ql;  K = 512;  N = 1536; }
    else if (id < 6144)   { id -= 4608;  W = Wf; Th = fh;  Tl = fl;  K = 512;  N = 512; }
    else if (id < 12288)  { id -= 6144;  W = W1; Th = w1h; Tl = w1l; K = 512;  N = 2048; }
    else                  { id -= 12288; W = W2; Th = w2h; Tl = w2l; K = 2048; N = 512; }
    const int tilesN = N >> 5, tilesK = K >> 5;
    const int l = id / (tilesN*tilesK);
    const int rem = id - l*(tilesN*tilesK);
    const int n0 = (rem % tilesN)*32, k0 = (rem / tilesN)*32;
    const int tx = threadIdx.x & 31, ty = threadIdx.x >> 5;
    const float* Wl = W + (size_t)l*K*N;
#pragma unroll
    for (int i = 0; i < 4; i++) {
        int k = k0 + ty*4 + i;
        tf[ty*4+i][tx] = Wl[(size_t)k*N + n0 + tx];
    }
    __syncthreads();
    __nv_bfloat16* Thl = Th + (size_t)l*K*N;
    __nv_bfloat16* Tll = Tl + (size_t)l*K*N;
#pragma unroll
    for (int i = 0; i < 4; i++) {
        int n = n0 + ty*4 + i;
        float v = tf[tx][ty*4+i];
        __nv_bfloat16 h, lo; split_bf16(v, h, lo);
        Thl[(size_t)n*K + k0 + tx] = h;
        Tll[(size_t)n*K + k0 + tx] = lo;
    }
}

// ---------------- mma.sync split-bf16 GEMM (R11 proven) ----------------
template<int EPI>
__global__ __launch_bounds__(256, 1) void mma_gemm_kernel(
    const __nv_bfloat16* __restrict__ Ahi, const __nv_bfloat16* __restrict__ Alo,
    const __nv_bfloat16* __restrict__ Bhi, const __nv_bfloat16* __restrict__ Blo,
    const float* __restrict__ bias,
    float* __restrict__ Cf,
    __nv_bfloat16* __restrict__ Chi, __nv_bfloat16* __restrict__ Clo,
    int N, int K)
{
    extern __shared__ char smem[];
    const unsigned sbase = smem_u32(smem);
    const int tid = threadIdx.x;
    const int wid = tid >> 5, lane = tid & 31;
    const int wr = wid & 3;
    const int wc = wid >> 2;
    const int bm = blockIdx.y * TM;
    const int bn = blockIdx.x * TN;

    const int la7  = lane & 7;
    const int la8  = (lane >> 3) & 1;
    const int la16 = lane >> 4;
    const unsigned aoff = (unsigned)((wr*32 + la7 + la8*8)*PADK + la16*8) * 2u;
    const unsigned boff = (unsigned)((wc*64 + la16*8 + la7)*PADK + la8*8) * 2u;

    const int lr = tid >> 3;
    const int lg = tid & 7;

    float acc[2][8][4];
#pragma unroll
    for (int ma = 0; ma < 2; ma++)
#pragma unroll
        for (int na = 0; na < 8; na++)
#pragma unroll
            for (int j = 0; j < 4; j++) acc[ma][na][j] = 0.0f;

    const int NC = K >> 6;

    {
        const unsigned st = sbase;
#pragma unroll
        for (int i = 0; i < 4; i++) {
            int r = lr + i*32;
            unsigned so = (unsigned)(r*144 + lg*16);
            size_t ga = (size_t)(bm + r)*K + lg*8;
            size_t gb = (size_t)(bn + r)*K + lg*8;
            cp16(st + so,                 Ahi + ga);
            cp16(st + MAT_BYTES + so,     Alo + ga);
            cp16(st + 2*MAT_BYTES + so,   Bhi + gb);
            cp16(st + 3*MAT_BYTES + so,   Blo + gb);
        }
        CP_COMMIT();
    }

    for (int c = 0; c < NC; c++) {
        if (c + 1 < NC) {
            const unsigned st = sbase + ((c+1) & 1)*STAGE_BYTES;
            const int k0 = (c+1)*KC;
#pragma unroll
            for (int i = 0; i < 4; i++) {
                int r = lr + i*32;
                unsigned so = (unsigned)(r*144 + lg*16);
                size_t ga = (size_t)(bm + r)*K + k0 + lg*8;
                size_t gb = (size_t)(bn + r)*K + k0 + lg*8;
                cp16(st + so,                 Ahi + ga);
                cp16(st + MAT_BYTES + so,     Alo + ga);
                cp16(st + 2*MAT_BYTES + so,   Bhi + gb);
                cp16(st + 3*MAT_BYTES + so,   Blo + gb);
            }
            CP_COMMIT();
            cp_wait<1>();
        } else {
            cp_wait<0>();
        }
        __syncthreads();

        const unsigned stg = sbase + (c & 1)*STAGE_BYTES;
        const unsigned sAh = stg + aoff;
        const unsigned sAl = stg + MAT_BYTES + aoff;
        const unsigned sBh = stg + 2*MAT_BYTES + boff;
        const unsigned sBl = stg + 3*MAT_BYTES + boff;

#pragma unroll
        for (int ks = 0; ks < 4; ks++) {
            const unsigned kb = (unsigned)(ks*32);
            unsigned ah[2][4], al[2][4];
#pragma unroll
            for (int ma = 0; ma < 2; ma++) {
                ldsm4(ah[ma], sAh + (unsigned)(ma*16*PADK*2) + kb);
                ldsm4(al[ma], sAl + (unsigned)(ma*16*PADK*2) + kb);
            }
            unsigned bh[4][4], bl[4][4];
#pragma unroll
            for (int nb = 0; nb < 4; nb++) {
                ldsm4(bh[nb], sBh + (unsigned)(nb*16*PADK*2) + kb);
                ldsm4(bl[nb], sBl + (unsigned)(nb*16*PADK*2) + kb);
            }
#pragma unroll
            for (int ma = 0; ma < 2; ma++)
#pragma unroll
                for (int na = 0; na < 8; na++)
                    mma16816(acc[ma][na], ah[ma], &bh[na>>1][(na&1)*2]);
#pragma unroll
            for (int ma = 0; ma < 2; ma++)
#pragma unroll
                for (int na = 0; na < 8; na++)
                    mma16816(acc[ma][na], ah[ma], &bl[na>>1][(na&1)*2]);
#pragma unroll
            for (int ma = 0; ma < 2; ma++)
#pragma unroll
                for (int na = 0; na < 8; na++)
                    mma16816(acc[ma][na], al[ma], &bh[na>>1][(na&1)*2]);
        }
        __syncthreads();
    }

    constexpr bool HASBIAS = (EPI == 1 || EPI == 2);
    constexpr bool RELU    = (EPI == 2);
    constexpr bool PAIR    = (EPI == 2 || EPI == 3);
#pragma unroll
    for (int ma = 0; ma < 2; ma++) {
        const int r0 = bm + wr*32 + ma*16 + (lane >> 2);
#pragma unroll
        for (int na = 0; na < 8; na++) {
            const int cc = bn + wc*64 + na*8 + (lane & 3)*2;
            float v0 = acc[ma][na][0], v1 = acc[ma][na][1];
            float v2 = acc[ma][na][2], v3 = acc[ma][na][3];
            if (HASBIAS) {
                float2 bv = *(const float2*)(bias + cc);
                v0 += bv.x; v1 += bv.y; v2 += bv.x; v3 += bv.y;
            }
            if (RELU) {
                v0 = fmaxf(v0, 0.0f); v1 = fmaxf(v1, 0.0f);
                v2 = fmaxf(v2, 0.0f); v3 = fmaxf(v3, 0.0f);
            }
            if (PAIR) {
                unsigned hi, lo;
                split2(v0, v1, hi, lo);
                *(unsigned*)(Chi + (size_t)r0*N + cc) = hi;
                *(unsigned*)(Clo + (size_t)r0*N + cc) = lo;
                split2(v2, v3, hi, lo);
                *(unsigned*)(Chi + (size_t)(r0+8)*N + cc) = hi;
                *(unsigned*)(Clo + (size_t)(r0+8)*N + cc) = lo;
            } else {
                *(float2*)(Cf + (size_t)r0*N + cc)     = make_float2(v0, v1);
                *(float2*)(Cf + (size_t)(r0+8)*N + cc) = make_float2(v2, v3);
            }
        }
    }
}

// ---------------- fused flash attention (ldmatrix frags, V via ldmatrix.trans) ----------------
__global__ __launch_bounds__(256, 1) void flash_kernel(
    const __nv_bfloat16* __restrict__ qhi, const __nv_bfloat16* __restrict__ qlo,
    const float* __restrict__ kbias,
    __nv_bfloat16* __restrict__ ohi, __nv_bfloat16* __restrict__ olo)
{
    extern __shared__ char smraw[];
    __nv_bfloat16* sm = (__nv_bfloat16*)smraw;
    const unsigned sb = smem_u32(sm);
    const int tid = threadIdx.x, wid = tid >> 5, lane = tid & 31;
    const int bh = blockIdx.y, b = bh >> 3, h = bh & 7;
    const int q0 = blockIdx.x * 128;
    const int koff = (lane & 3)*2;
    const int r_base = wid*16 + (lane >> 2);

    const int la7  = lane & 7;
    const int la8  = (lane >> 3) & 1;
    const int la16 = lane >> 4;
    // Q (A operand, 16 rows per warp): tiles (r,k),(r+8,k),(r,k+8),(r+8,k+8)
    const unsigned qoff = (unsigned)((wid*16 + la7 + la8*8)*FPAD + la16*8) * 2u;
    // K (B non-trans): per nb: rows nb*16 + la16*8 + la7, k col la8*8
    const unsigned kboff = (unsigned)((la16*8 + la7)*FPAD + la8*8) * 2u;
    // V (B trans, [s][d] layout): tile t=lane>>3 -> s row (t&1)*8+la7, d col (t>>1)*8
    const unsigned vboff = (unsigned)((la8*8 + la7)*FPAD + la16*8) * 2u;

    auto prefetch_kv = [&](int t, int s){
        const int g = tid & 7;
        const int kt0 = t*64;
#pragma unroll
        for (int i = 0; i < 2; i++) {
            int r = (tid >> 3) + i*32;
            size_t gk = (size_t)(b*SEQ + kt0 + r)*1536 + 512 + h*64 + g*8;
            cp16(sb + 2*(KS_HI(s) + r*FPAD + g*8), qhi + gk);
            cp16(sb + 2*(KS_LO(s) + r*FPAD + g*8), qlo + gk);
            size_t gv = (size_t)(b*SEQ + kt0 + r)*1536 + 1024 + h*64 + g*8;
            cp16(sb + 2*(VS_HI(s) + r*FPAD + g*8), qhi + gv);
            cp16(sb + 2*(VS_LO(s) + r*FPAD + g*8), qlo + gv);
        }
        if (tid >= 240) {
            int j = tid - 240;
            cp16(sb + 2*BI_F(s) + j*16, kbias + b*SEQ + kt0 + j*4);
        }
    };

    {
        const int g = tid & 7;
#pragma unroll
        for (int i = 0; i < 4; i++) {
            int r = (tid >> 3) + i*32;
            size_t gq = (size_t)(b*SEQ + q0 + r)*1536 + h*64 + g*8;
            cp16(sb + 2*(Q_HI + r*FPAD + g*8), qhi + gq);
            cp16(sb + 2*(Q_LO + r*FPAD + g*8), qlo + gq);
        }
        prefetch_kv(0, 0);
        CP_COMMIT();
    }

    float m0 = -1e30f, m1 = -1e30f, l0 = 0.0f, l1 = 0.0f;
    float acc_o[8][4];
#pragma unroll
    for (int na = 0; na < 8; na++)
#pragma unroll
        for (int j = 0; j < 4; j++) acc_o[na][j] = 0.0f;

    for (int t = 0; t < NTILE; t++) {
        if (t + 1 < NTILE) { prefetch_kv(t+1, (t+1)&1); CP_COMMIT(); cp_wait<1>(); }
        else               { cp_wait<0>(); }
        __syncthreads();
        const int s = t & 1;
        const unsigned sQh = sb + 2*Q_HI + qoff;
        const unsigned sQl = sb + 2*Q_LO + qoff;
        const unsigned sKh = sb + 2*KS_HI(s) + kboff;
        const unsigned sKl = sb + 2*KS_LO(s) + kboff;
        const unsigned sVh = sb + 2*VS_HI(s) + vboff;
        const unsigned sVl = sb + 2*VS_LO(s) + vboff;
        const float* bsm = (const float*)(sm + BI_F(s));

        // S = Q K^T (3-product split)
        float sc[8][4];
#pragma unroll
        for (int na = 0; na < 8; na++)
#pragma unroll
            for (int j = 0; j < 4; j++) sc[na][j] = 0.0f;

#pragma unroll
        for (int kc = 0; kc < 4; kc++) {
            const unsigned kb = (unsigned)(kc*32);
            unsigned ah[4], al[4];
            ldsm4(ah, sQh + kb);
            ldsm4(al, sQl + kb);
            unsigned kbh[4][4], kbl[4][4];
#pragma unroll
            for (int nb = 0; nb < 4; nb++) {
                ldsm4(kbh[nb], sKh + (unsigned)(nb*16*FPAD*2) + kb);
                ldsm4(kbl[nb], sKl + (unsigned)(nb*16*FPAD*2) + kb);
            }
#pragma unroll
            for (int na = 0; na < 8; na++)
                mma16816(sc[na], ah, &kbh[na>>1][(na&1)*2]);
#pragma unroll
            for (int na = 0; na < 8; na++)
                mma16816(sc[na], ah, &kbl[na>>1][(na&1)*2]);
#pragma unroll
            for (int na = 0; na < 8; na++)
                mma16816(sc[na], al, &kbh[na>>1][(na&1)*2]);
        }

        // key-mask bias
#pragma unroll
        for (int na = 0; na < 8; na++) {
            float b0 = bsm[na*8 + koff], b1 = bsm[na*8 + koff + 1];
            sc[na][0] += b0; sc[na][1] += b1;
            sc[na][2] += b0; sc[na][3] += b1;
        }

        // online softmax (rows r_base and r_base+8)
        float mx0 = -1e30f, mx1 = -1e30f;
#pragma unroll
        for (int na = 0; na < 8; na++) {
            mx0 = fmaxf(mx0, fmaxf(sc[na][0], sc[na][1]));
            mx1 = fmaxf(mx1, fmaxf(sc[na][2], sc[na][3]));
        }
        mx0 = fmaxf(mx0, __shfl_xor_sync(0xffffffffu, mx0, 1));
        mx0 = fmaxf(mx0, __shfl_xor_sync(0xffffffffu, mx0, 2));
        mx1 = fmaxf(mx1, __shfl_xor_sync(0xffffffffu, mx1, 1));
        mx1 = fmaxf(mx1, __shfl_xor_sync(0xffffffffu, mx1, 2));
        float mn0 = fmaxf(m0, mx0), mn1 = fmaxf(m1, mx1);
        float e0 = __expf(m0 - mn0), e1 = __expf(m1 - mn1);
        m0 = mn0; m1 = mn1;
        float s0 = 0.0f, s1 = 0.0f;
#pragma unroll
        for (int na = 0; na < 8; na++) {
            sc[na][0] = __expf(sc[na][0] - mn0);
            sc[na][1] = __expf(sc[na][1] - mn0);
            sc[na][2] = __expf(sc[na][2] - mn1);
            sc[na][3] = __expf(sc[na][3] - mn1);
            s0 += sc[na][0] + sc[na][1];
            s1 += sc[na][2] + sc[na][3];
        }
        s0 += __shfl_xor_sync(0xffffffffu, s0, 1);
        s0 += __shfl_xor_sync(0xffffffffu, s0, 2);
        s1 += __shfl_xor_sync(0xffffffffu, s1, 1);
        s1 += __shfl_xor_sync(0xffffffffu, s1, 2);
        l0 = l0*e0 + s0;
        l1 = l1*e1 + s1;
#pragma unroll
        for (int na = 0; na < 8; na++) {
            acc_o[na][0] *= e0; acc_o[na][1] *= e0;
            acc_o[na][2] *= e1; acc_o[na][3] *= e1;
        }

        // O += P V ; V frags via ldmatrix.trans on [s][d] tile
#pragma unroll
        for (int kc = 0; kc < 4; kc++) {
            unsigned ph[4], pl[4];
            split2(sc[2*kc][0],   sc[2*kc][1],   ph[0], pl[0]);
            split2(sc[2*kc][2],   sc[2*kc][3],   ph[1], pl[1]);
            split2(sc[2*kc+1][0], sc[2*kc+1][1], ph[2], pl[2]);
            split2(sc[2*kc+1][2], sc[2*kc+1][3], ph[3], pl[3]);
            const unsigned sB = (unsigned)(kc*16*FPAD*2);
            unsigned vbh[4][4], vbl[4][4];
#pragma unroll
            for (int nb = 0; nb < 4; nb++) {
                ldsm4t(vbh[nb], sVh + sB + (unsigned)(nb*32));
                ldsm4t(vbl[nb], sVl + sB + (unsigned)(nb*32));
            }
#pragma unroll
            for (int na = 0; na < 8; na++)
                mma16816(acc_o[na], ph, &vbh[na>>1][(na&1)*2]);
#pragma unroll
            for (int na = 0; na < 8; na++)
                mma16816(acc_o[na], ph, &vbl[na>>1][(na&1)*2]);
#pragma unroll
            for (int na = 0; na < 8; na++)
                mma16816(acc_o[na], pl, &vbh[na>>1][(na&1)*2]);
        }
        __syncthreads();
    }

    const float inv0 = 1.0f / l0, inv1 = 1.0f / l1;
    const size_t row0 = (size_t)(b*SEQ + q0 + r_base);
#pragma unroll
    for (int na = 0; na < 8; na++) {
        const int col = h*64 + na*8 + koff;
        unsigned hi, lo;
        split2(acc_o[na][0]*inv0, acc_o[na][1]*inv0, hi, lo);
        *(unsigned*)(ohi + row0*DMODEL + col) = hi;
        *(unsigned*)(olo + row0*DMODEL + col) = lo;
        split2(acc_o[na][2]*inv1, acc_o[na][3]*inv1, hi, lo);
        *(unsigned*)(ohi + (row0+8)*DMODEL + col) = hi;
        *(unsigned*)(olo + (row0+8)*DMODEL + col) = lo;
    }
}

// ---------------- positional embedding + pair split + key-mask bias ----------------
__global__ void posembed_kernel(const float* __restrict__ xin,
                                const int* __restrict__ mask,
                                float* __restrict__ xout,
                                __nv_bfloat16* __restrict__ xhi,
                                __nv_bfloat16* __restrict__ xlo,
                                float* __restrict__ kb)
{
    int b = blockIdx.x;
    int tid = threadIdx.x;                    // 1024 threads
    __shared__ int sc[SEQ];
    int valid = (mask[b*SEQ + tid] != 0) ? 1 : 0;
    kb[b*SEQ + tid] = valid ? 0.0f : -1e30f;
    sc[tid] = valid;
    __syncthreads();
    for (int off = 1; off < SEQ; off <<= 1) {
        int v = (tid >= off) ? sc[tid - off] : 0;
        __syncthreads();
        sc[tid] += v;
        __syncthreads();
    }
    int pos = sc[tid] * valid;
    __syncthreads();
    sc[tid] = pos;
    __syncthreads();

    const float cfreq = -logf(10000.0f) / 255.0f;
    for (int it = 0; it < (SEQ*DMODEL)/SEQ; it++) {
        int idx = it*SEQ + tid;
        int s = idx >> 9;
        int j = idx & 511;
        int p = sc[s];
        size_t g = ((size_t)b*SEQ + s)*DMODEL + j;
        float add = 0.0f;
        if (p > 0) {
            float fr  = expf((float)(j & 255) * cfreq);
            float ang = (float)p * fr;
            add = (j < 256) ? sinf(ang) : cosf(ang);
        }
        float v = xin[g] + add;
        xout[g] = v;
        __nv_bfloat16 h, l; split_bf16(v, h, l);
        xhi[g] = h; xlo[g] = l;
    }
}

// ---------------- out = LN(a + r) * g + b ; warp-per-row, shfl-only ----------------
__global__ __launch_bounds__(256) void ln_kernel(
    const float* __restrict__ a, const float* __restrict__ r,
    const float* __restrict__ g, const float* __restrict__ be,
    float* __restrict__ out,
    __nv_bfloat16* __restrict__ ohi, __nv_bfloat16* __restrict__ olo)
{
    const int row = blockIdx.x*8 + (threadIdx.x >> 5);
    const int lane = threadIdx.x & 31;
    const size_t base = (size_t)row*DMODEL;
    const float4* a4 = (const float4*)(a + base);
    const float4* r4 = (const float4*)(r + base);

    float4 x[4];
    float s = 0.0f;
#pragma unroll
    for (int k = 0; k < 4; k++) {
        float4 va = a4[lane + k*32];
        float4 vr = r4[lane + k*32];
        x[k] = make_float4(va.x+vr.x, va.y+vr.y, va.z+vr.z, va.w+vr.w);
        s += x[k].x + x[k].y + x[k].z + x[k].w;
    }
#pragma unroll
    for (int o = 16; o; o >>= 1) s += __shfl_xor_sync(0xffffffffu, s, o);
    const float mu = s * (1.0f/512.0f);

    float s2 = 0.0f;
#pragma unroll
    for (int k = 0; k < 4; k++) {
        x[k].x -= mu; x[k].y -= mu; x[k].z -= mu; x[k].w -= mu;
        s2 += x[k].x*x[k].x + x[k].y*x[k].y + x[k].z*x[k].z + x[k].w*x[k].w;
    }
#pragma unroll
    for (int o = 16; o; o >>= 1) s2 += __shfl_xor_sync(0xffffffffu, s2, o);
    const float inv = rsqrtf(s2 * (1.0f/512.0f) + 1e-5f);

    const float4* g4 = (const float4*)g;
    const float4* b4 = (const float4*)be;
    float4* o4 = (float4*)(out + base);
    uint2* oh2 = (uint2*)(ohi + base);
    uint2* ol2 = (uint2*)(olo + base);
#pragma unroll
    for (int k = 0; k < 4; k++) {
        float4 gg = g4[lane + k*32];
        float4 bb = b4[lane + k*32];
        float4 o;
        o.x = x[k].x*inv*gg.x + bb.x;
        o.y = x[k].y*inv*gg.y + bb.y;
        o.z = x[k].z*inv*gg.z + bb.z;
        o.w = x[k].w*inv*gg.w + bb.w;
        o4[lane + k*32] = o;
        unsigned h0, l0, h1, l1;
        split2(o.x, o.y, h0, l0);
        split2(o.z, o.w, h1, l1);
        oh2[lane + k*32] = make_uint2(h0, h1);
        ol2[lane + k*32] = make_uint2(l0, l1);
    }
}

// ---------------- driver ----------------
extern "C" void kernel_launch(void* const* d_in, const int* in_sizes, int n_in,
                              void* d_out, int out_size)
{
    const float* x_in = (const float*)d_in[0];
    const int*   mask = (const int*)d_in[3];
    const float* Wqkv = (const float*)d_in[4];
    const float* Wfc  = (const float*)d_in[5];
    const float* bfc  = (const float*)d_in[6];
    const float* ln1g = (const float*)d_in[7];
    const float* ln1b = (const float*)d_in[8];
    const float* ln2g = (const float*)d_in[9];
    const float* ln2b = (const float*)d_in[10];
    const float* W1   = (const float*)d_in[11];
    const float* b1   = (const float*)d_in[12];
    const float* W2   = (const float*)d_in[13];
    const float* b2   = (const float*)d_in[14];

    float *px, *ptmp, *pkb;
    __nv_bfloat16 *pxhi, *pxlo, *pqh, *pql, *paohi, *paolo, *pfhi, *pflo;
    __nv_bfloat16 *wqh, *wql, *wfh, *wfl, *w1h, *w1l, *w2h, *w2l;
    cudaGetSymbolAddress((void**)&px,    g_x);
    cudaGetSymbolAddress((void**)&pxhi,  g_xhi);
    cudaGetSymbolAddress((void**)&pxlo,  g_xlo);
    cudaGetSymbolAddress((void**)&pqh,   g_qkvhi);
    cudaGetSymbolAddress((void**)&pql,   g_qkvlo);
    cudaGetSymbolAddress((void**)&pkb,   g_kbias);
    cudaGetSymbolAddress((void**)&paohi, g_aohi);
    cudaGetSymbolAddress((void**)&paolo, g_aolo);
    cudaGetSymbolAddress((void**)&ptmp,  g_tmp);
    cudaGetSymbolAddress((void**)&pfhi,  g_fhi);
    cudaGetSymbolAddress((void**)&pflo,  g_flo);
    cudaGetSymbolAddress((void**)&wqh,   g_wqkvhi);
    cudaGetSymbolAddress((void**)&wql,   g_wqkvlo);
    cudaGetSymbolAddress((void**)&wfh,   g_wfchi);
    cudaGetSymbolAddress((void**)&wfl,   g_wfclo);
    cudaGetSymbolAddress((void**)&w1h,   g_w1hi);
    cudaGetSymbolAddress((void**)&w1l,   g_w1lo);
    cudaGetSymbolAddress((void**)&w2h,   g_w2hi);
    cudaGetSymbolAddress((void**)&w2l,   g_w2lo);

    cudaFuncSetAttribute(mma_gemm_kernel<1>, cudaFuncAttributeMaxDynamicSharedMemorySize, GEMM_SMEM);
    cudaFuncSetAttribute(mma_gemm_kernel<2>, cudaFuncAttributeMaxDynamicSharedMemorySize, GEMM_SMEM);
    cudaFuncSetAttribute(mma_gemm_kernel<3>, cudaFuncAttributeMaxDynamicSharedMemorySize, GEMM_SMEM);
    cudaFuncSetAttribute(flash_kernel, cudaFuncAttributeMaxDynamicSharedMemorySize, FLASH_SMEM);

    wprep_all_kernel<<<18432, 256>>>(Wqkv, Wfc, W1, W2,
                                     wqh, wql, wfh, wfl, w1h, w1l, w2h, w2l);

    posembed_kernel<<<BATCH, SEQ>>>(x_in, mask, px, pxhi, pxlo, pkb);

    for (int l = 0; l < NLAYER; l++) {
        size_t oq = (size_t)l*3*DMODEL*DMODEL;
        size_t of = (size_t)l*DMODEL*DMODEL;
        size_t o1 = (size_t)l*DFF*DMODEL;
        size_t o2 = (size_t)l*DMODEL*DFF;
        // QKV -> bf16 hi/lo pair   [8192,512] x [1536,512]^T
        mma_gemm_kernel<3><<<dim3(3*DMODEL/TN, NTOK/TM), 256, GEMM_SMEM>>>(
            pxhi, pxlo, wqh + oq, wql + oq, nullptr, nullptr, pqh, pql, 3*DMODEL, DMODEL);
        // fused attention (V loaded + transposed in-kernel via ldmatrix.trans)
        flash_kernel<<<dim3(SEQ/128, BATCH*NHEAD), 256, FLASH_SMEM>>>(
            pqh, pql, pkb, paohi, paolo);
        // proj + bias -> fp32
        mma_gemm_kernel<1><<<dim3(DMODEL/TN, NTOK/TM), 256, GEMM_SMEM>>>(
            paohi, paolo, wfh + of, wfl + of, bfc + l*DMODEL, ptmp, nullptr, nullptr, DMODEL, DMODEL);
        ln_kernel<<<NTOK/8, 256>>>(ptmp, px, ln1g + l*DMODEL, ln1b + l*DMODEL, px, pxhi, pxlo);
        // FFN up + relu -> bf16 pair
        mma_gemm_kernel<2><<<dim3(DFF/TN, NTOK/TM), 256, GEMM_SMEM>>>(
            pxhi, pxlo, w1h + o1, w1l + o1, b1 + l*DFF, nullptr, pfhi, pflo, DFF, DMODEL);
        // FFN down + bias -> fp32
        mma_gemm_kernel<1><<<dim3(DMODEL/TN, NTOK/TM), 256, GEMM_SMEM>>>(
            pfhi, pflo, w2h + o2, w2l + o2, b2 + l*DMODEL, ptmp, nullptr, nullptr, DMODEL, DFF);
        ln_kernel<<<NTOK/8, 256>>>(ptmp, px, ln2g + l*DMODEL, ln2b + l*DMODEL, px, pxhi, pxlo);
    }

    cudaMemcpyAsync(d_out, px, (size_t)NTOK*DMODEL*sizeof(float),
                    cudaMemcpyDeviceToDevice);
}